// round 2
// baseline (speedup 1.0000x reference)
#include <cuda_runtime.h>

// ---------------- problem constants ----------------
#define BQ    8
#define CCH   256
#define HFULL 160
#define WFULL 160
#define HHALF 80
#define WHALF 80
#define HWQ   6400          // 80*80
#define MTOT  51200         // 8*6400
#define K1    1024
#define N1    256
#define K2    256
#define N2    1024
#define NSEG  25            // 6400 / 256

// ---------------- scratch (device globals; no allocation allowed) --------
__device__ __align__(16) float g_W1p[K1 * N1];        // [k][o], k = c*4+q
__device__ __align__(16) float g_bias1[N1];
__device__ __align__(16) float g_W2p[K2 * N2];        // [k][j], j = c'*4+g (permuted)
__device__ __align__(16) float g_bias2p[N2];
__device__ __align__(16) float g_fused[(long)MTOT * CCH]; // 52.4 MB, [m][c]
__device__ __align__(16) float g_avg_sp[MTOT];
__device__ __align__(16) float g_max_sp[MTOT];
__device__ __align__(16) float g_gate[MTOT];
__device__ __align__(16) float g_chsum_part[NSEG * BQ * CCH];
__device__ __align__(16) float g_chmax_part[NSEG * BQ * CCH];
__device__ __align__(16) float g_chmap[BQ * CCH];

// ---------------- f32x2 helpers (Blackwell packed fp32 pipe) -------------
__device__ __forceinline__ unsigned long long pack2(float lo, float hi) {
    unsigned long long r;
    asm("mov.b64 %0, {%1, %2};" : "=l"(r) : "f"(lo), "f"(hi));
    return r;
}
__device__ __forceinline__ void unpack2(unsigned long long v, float& lo, float& hi) {
    asm("mov.b64 {%0, %1}, %2;" : "=f"(lo), "=f"(hi) : "l"(v));
}
__device__ __forceinline__ unsigned long long fma2(unsigned long long a,
                                                   unsigned long long b,
                                                   unsigned long long c) {
    unsigned long long d;
    asm("fma.rn.f32x2 %0, %1, %2, %3;" : "=l"(d) : "l"(a), "l"(b), "l"(c));
    return d;
}

// ---------------- K0a: prep fusion weights (fold DWT + BN1) --------------
// wav coefficient signs per raw-pixel q in {a,b,c,d}:
//   coeff(q) = 0.5*(w_ll + s_lh*w_lh + s_hl*w_hl + s_hh*w_hh)
__global__ void prep1(const float* __restrict__ fw, const float* __restrict__ fb,
                      const float* __restrict__ g1, const float* __restrict__ b1,
                      const float* __restrict__ m1, const float* __restrict__ v1) {
    int idx = blockIdx.x * blockDim.x + threadIdx.x;
    if (idx >= K1 * N1) return;
    int o = idx & 255;
    int k = idx >> 8;            // k = c*4 + q
    int c = k >> 2, q = k & 3;
    float inv = g1[o] * rsqrtf(v1[o] + 1e-5f);
    float slh = (q < 2) ? 1.f : -1.f;
    float shl = ((q & 1) == 0) ? 1.f : -1.f;
    float shh = slh * shl;
    float val = fw[o * 1024 + c]
              + slh * fw[o * 1024 + 256 + c]
              + shl * fw[o * 1024 + 512 + c]
              + shh * fw[o * 1024 + 768 + c];
    g_W1p[k * 256 + o] = 0.5f * inv * val;
    if (k == 0) g_bias1[o] = fb[o] * inv + b1[o] - m1[o] * inv;
}

// ---------------- K0b: prep proj weights (fold BN2, permute for iDWT) ----
__global__ void prep2(const float* __restrict__ pw, const float* __restrict__ pb,
                      const float* __restrict__ g2, const float* __restrict__ b2,
                      const float* __restrict__ m2, const float* __restrict__ v2) {
    int idx = blockIdx.x * blockDim.x + threadIdx.x;
    if (idx >= K2 * N2) return;
    int j = idx & 1023;          // j = c'*4 + g
    int k = idx >> 10;           // input channel
    int o = (j & 3) * 256 + (j >> 2);   // original projected channel
    float inv = g2[o] * rsqrtf(v2[o] + 1e-5f);
    g_W2p[k * 1024 + j] = pw[o * 256 + k] * inv;
    if (k == 0) g_bias2p[j] = pb[o] * inv + b2[o] - m2[o] * inv;
}

// ---------------- K1: GEMM1 (DWT-on-the-fly, bias+BN folded, relu) -------
// fused[m][c] = relu( sum_k A[m,k] * W1p[k][c] + bias1[c] )
// A[m, c*4+q] = x[b, c, 2h+dy, 2w+dx]
__global__ __launch_bounds__(256) void gemm1(const float* __restrict__ x) {
    __shared__ float As[16 * 128];
    __shared__ float Bs[16 * 128];
    const int tid = threadIdx.x;
    const int m0 = blockIdx.x * 128;
    const int n0 = blockIdx.y * 128;

    const int m_l = tid & 127;
    const int k_half = tid >> 7;
    const int m = m0 + m_l;
    const int bb = m / HWQ;
    const int hw = m % HWQ;
    const int h = hw / WHALF, w = hw % WHALF;
    const float* px = x + ((bb * 256) * 160 + 2 * h) * 160 + 2 * w;

    const int tm = tid >> 4, tn = tid & 15;

    unsigned long long acc[8][4];
#pragma unroll
    for (int i = 0; i < 8; i++)
#pragma unroll
        for (int p = 0; p < 4; p++) acc[i][p] = pack2(0.f, 0.f);

    for (int k0 = 0; k0 < K1; k0 += 16) {
#pragma unroll
        for (int r = 0; r < 8; r++) {
            int kl = k_half * 8 + r;
            int k = k0 + kl;
            As[kl * 128 + m_l] = px[(k >> 2) * 25600 + ((k & 2) ? 160 : 0) + (k & 1)];
            Bs[kl * 128 + m_l] = g_W1p[k * 256 + n0 + m_l];
        }
        __syncthreads();
#pragma unroll
        for (int kk = 0; kk < 16; kk++) {
            const float4 a0 = *(const float4*)(As + kk * 128 + tm * 8);
            const float4 a1 = *(const float4*)(As + kk * 128 + tm * 8 + 4);
            const float4 b0 = *(const float4*)(Bs + kk * 128 + tn * 8);
            const float4 b1 = *(const float4*)(Bs + kk * 128 + tn * 8 + 4);
            unsigned long long bp0 = pack2(b0.x, b0.y);
            unsigned long long bp1 = pack2(b0.z, b0.w);
            unsigned long long bp2 = pack2(b1.x, b1.y);
            unsigned long long bp3 = pack2(b1.z, b1.w);
            float av[8] = {a0.x, a0.y, a0.z, a0.w, a1.x, a1.y, a1.z, a1.w};
#pragma unroll
            for (int i = 0; i < 8; i++) {
                unsigned long long ad = pack2(av[i], av[i]);
                acc[i][0] = fma2(ad, bp0, acc[i][0]);
                acc[i][1] = fma2(ad, bp1, acc[i][1]);
                acc[i][2] = fma2(ad, bp2, acc[i][2]);
                acc[i][3] = fma2(ad, bp3, acc[i][3]);
            }
        }
        __syncthreads();
    }

    float bias[8];
    *(float4*)&bias[0] = *(const float4*)&g_bias1[n0 + tn * 8];
    *(float4*)&bias[4] = *(const float4*)&g_bias1[n0 + tn * 8 + 4];
#pragma unroll
    for (int i = 0; i < 8; i++) {
        float v[8];
#pragma unroll
        for (int p = 0; p < 4; p++) unpack2(acc[i][p], v[2 * p], v[2 * p + 1]);
#pragma unroll
        for (int j = 0; j < 8; j++) v[j] = fmaxf(v[j] + bias[j], 0.f);
        int mi = m0 + tm * 8 + i;
        float* dst = g_fused + (long)mi * 256 + n0 + tn * 8;
        *(float4*)dst       = make_float4(v[0], v[1], v[2], v[3]);
        *(float4*)(dst + 4) = make_float4(v[4], v[5], v[6], v[7]);
    }
}

// ---------------- K2: per-pixel channel mean/max --------------------------
__global__ void spstats() {
    int wi = threadIdx.x >> 5, lane = threadIdx.x & 31;
    int m = blockIdx.x * 8 + wi;
    const float4* f = (const float4*)(g_fused + (long)m * 256);
    float s = 0.f, mx = -1e30f;
#pragma unroll
    for (int r = 0; r < 2; r++) {
        float4 v = f[lane + r * 32];
        s += v.x + v.y + v.z + v.w;
        mx = fmaxf(mx, fmaxf(fmaxf(v.x, v.y), fmaxf(v.z, v.w)));
    }
#pragma unroll
    for (int off = 16; off; off >>= 1) {
        s += __shfl_xor_sync(0xffffffffu, s, off);
        mx = fmaxf(mx, __shfl_xor_sync(0xffffffffu, mx, off));
    }
    if (lane == 0) {
        g_avg_sp[m] = s * (1.f / 256.f);
        g_max_sp[m] = mx;
    }
}

// ---------------- K3: 7x7 spatial conv + sigmoid --------------------------
__global__ void spconv(const float* __restrict__ sa_w) {
    __shared__ float sw[98];
    if (threadIdx.x < 98) sw[threadIdx.x] = sa_w[threadIdx.x];
    __syncthreads();
    int m = blockIdx.x * 256 + threadIdx.x;
    int bb = m / HWQ, hw = m % HWQ;
    int h = hw / WHALF, w = hw % WHALF;
    float acc = 0.f;
#pragma unroll
    for (int ky = 0; ky < 7; ky++) {
        int y = h + ky - 3;
        if ((unsigned)y < 80u) {
#pragma unroll
            for (int kx = 0; kx < 7; kx++) {
                int xx = w + kx - 3;
                if ((unsigned)xx < 80u) {
                    int mi = bb * HWQ + y * WHALF + xx;
                    acc += g_avg_sp[mi] * sw[ky * 7 + kx]
                         + g_max_sp[mi] * sw[49 + ky * 7 + kx];
                }
            }
        }
    }
    g_gate[m] = 1.f / (1.f + expf(-acc));
}

// ---------------- K4: per-(b,c) sum/max of gate*fused, partials -----------
__global__ void chstats_part() {
    int bid = blockIdx.x;                 // 8*8*25 = 1600
    int bb = bid / 200;
    int rem = bid % 200;
    int cg = rem / NSEG;
    int seg = rem % NSEG;
    int cl = threadIdx.x & 31;
    int r0 = threadIdx.x >> 5;
    int c = cg * 32 + cl;
    float s = 0.f, mx = 0.f;              // values are >= 0 (relu * sigmoid)
    for (int r = r0; r < 256; r += 8) {
        int m = bb * HWQ + seg * 256 + r;
        float v = g_gate[m] * g_fused[(long)m * 256 + c];
        s += v;
        mx = fmaxf(mx, v);
    }
    __shared__ float ss[256], sm_[256];
    ss[threadIdx.x] = s;
    sm_[threadIdx.x] = mx;
    __syncthreads();
    if (r0 == 0) {
#pragma unroll
        for (int r = 1; r < 8; r++) {
            s += ss[r * 32 + cl];
            mx = fmaxf(mx, sm_[r * 32 + cl]);
        }
        g_chsum_part[(seg * BQ + bb) * 256 + c] = s;
        g_chmax_part[(seg * BQ + bb) * 256 + c] = mx;
    }
}

// ---------------- K5: finalize stats + channel MLP + sigmoid --------------
__global__ void chmlp(const float* __restrict__ w1, const float* __restrict__ w2) {
    int bb = blockIdx.x;
    int tid = threadIdx.x;
    __shared__ float sA[256], sM[256], sH[32];
    float s = 0.f, mx = 0.f;
    for (int seg = 0; seg < NSEG; seg++) {
        s += g_chsum_part[(seg * BQ + bb) * 256 + tid];
        mx = fmaxf(mx, g_chmax_part[(seg * BQ + bb) * 256 + tid]);
    }
    sA[tid] = s * (1.f / 6400.f);
    sM[tid] = mx;
    __syncthreads();
    int warp = tid >> 5, lane = tid & 31;
#pragma unroll
    for (int it = 0; it < 4; it++) {
        int t = warp * 4 + it;            // 0..31
        int u = t & 15, which = t >> 4;
        const float* vec = which ? sM : sA;
        float d = 0.f;
        for (int cc = lane; cc < 256; cc += 32) d += w1[u * 256 + cc] * vec[cc];
#pragma unroll
        for (int off = 16; off; off >>= 1) d += __shfl_xor_sync(0xffffffffu, d, off);
        if (lane == 0) sH[t] = fmaxf(d, 0.f);
    }
    __syncthreads();
    float o = 0.f;
#pragma unroll
    for (int u = 0; u < 16; u++) o += w2[tid * 16 + u] * (sH[u] + sH[16 + u]);
    g_chmap[bb * 256 + tid] = 1.f / (1.f + expf(-o));
}

// ---------------- K6: GEMM2 with fused ch/sp gating + iDWT + identity -----
__global__ __launch_bounds__(256) void gemm2(const float* __restrict__ x,
                                             float* __restrict__ out) {
    __shared__ float As[128 * 17];        // [m][k], padded
    __shared__ float Bs[16 * 128];        // [k][j]
    __shared__ float S[16 * 128];         // epilogue staging [j_l][m]
    __shared__ float gate_s[128];
    __shared__ float cmap_s[256];
    const int tid = threadIdx.x;
    const int m0 = blockIdx.x * 128;
    const int n0 = blockIdx.y * 128;
    const int bb = m0 / HWQ;

    if (tid < 128) gate_s[tid] = g_gate[m0 + tid];
    cmap_s[tid] = g_chmap[bb * 256 + tid];
    __syncthreads();

    const int tm = tid >> 4, tn = tid & 15;

    unsigned long long acc[8][4];
#pragma unroll
    for (int i = 0; i < 8; i++)
#pragma unroll
        for (int p = 0; p < 4; p++) acc[i][p] = pack2(0.f, 0.f);

    for (int k0 = 0; k0 < K2; k0 += 16) {
#pragma unroll
        for (int r = 0; r < 8; r++) {
            int e = tid + r * 256;
            int ml = e >> 4, kl = e & 15;
            As[ml * 17 + kl] =
                g_fused[(long)(m0 + ml) * 256 + k0 + kl] * gate_s[ml] * cmap_s[k0 + kl];
            int nl = e & 127, kl2 = e >> 7;
            Bs[kl2 * 128 + nl] = g_W2p[(k0 + kl2) * 1024 + n0 + nl];
        }
        __syncthreads();
#pragma unroll
        for (int kk = 0; kk < 16; kk++) {
            const float4 b0 = *(const float4*)(Bs + kk * 128 + tn * 8);
            const float4 b1 = *(const float4*)(Bs + kk * 128 + tn * 8 + 4);
            unsigned long long bp0 = pack2(b0.x, b0.y);
            unsigned long long bp1 = pack2(b0.z, b0.w);
            unsigned long long bp2 = pack2(b1.x, b1.y);
            unsigned long long bp3 = pack2(b1.z, b1.w);
#pragma unroll
            for (int i = 0; i < 8; i++) {
                float a = As[(tm * 8 + i) * 17 + kk];
                unsigned long long ad = pack2(a, a);
                acc[i][0] = fma2(ad, bp0, acc[i][0]);
                acc[i][1] = fma2(ad, bp1, acc[i][1]);
                acc[i][2] = fma2(ad, bp2, acc[i][2]);
                acc[i][3] = fma2(ad, bp3, acc[i][3]);
            }
        }
        __syncthreads();
    }

    // bias (permuted order) for this thread's 8 columns
    float bias[8];
    *(float4*)&bias[0] = *(const float4*)&g_bias2p[n0 + tn * 8];
    *(float4*)&bias[4] = *(const float4*)&g_bias2p[n0 + tn * 8 + 4];

    // Epilogue in 8 chunks of 16 j-columns: bias+relu -> stage -> iDWT -> out
    const int myg = tn >> 1;
    const int jhalf = tn & 1;
    for (int g = 0; g < 8; g++) {
        if (myg == g) {
#pragma unroll
            for (int i = 0; i < 8; i++) {
                float v[8];
#pragma unroll
                for (int p = 0; p < 4; p++) unpack2(acc[i][p], v[2 * p], v[2 * p + 1]);
#pragma unroll
                for (int j = 0; j < 8; j++) {
                    float val = fmaxf(v[j] + bias[j], 0.f);
                    S[(jhalf * 8 + j) * 128 + tm * 8 + i] = val;
                }
            }
        }
        __syncthreads();
        // chunk holds 4 c' channels x 128 pixels, all 4 wavelet comps each
#pragma unroll
        for (int pp = 0; pp < 2; pp++) {
            int p = tid + pp * 256;          // 0..511
            int m_l = p & 127;
            int cl = p >> 7;                 // 0..3
            float ll = S[(cl * 4 + 0) * 128 + m_l];
            float lh = S[(cl * 4 + 1) * 128 + m_l];
            float hl = S[(cl * 4 + 2) * 128 + m_l];
            float hh = S[(cl * 4 + 3) * 128 + m_l];
            float oa = 0.5f * (ll + lh + hl + hh);
            float ob = 0.5f * (ll + lh - hl - hh);
            float oc = 0.5f * (ll - lh + hl - hh);
            float od = 0.5f * (ll - lh - hl + hh);
            int m = m0 + m_l;
            int hw = m % HWQ;
            int h = hw / WHALF, w = hw % WHALF;
            int cp = ((n0 + g * 16) >> 2) + cl;
            long base = (((long)bb * 256 + cp) * 160 + 2 * h) * 160 + 2 * w;
            float2 x01 = *(const float2*)(x + base);
            float2 x23 = *(const float2*)(x + base + 160);
            *(float2*)(out + base)       = make_float2(oa + x01.x, ob + x01.y);
            *(float2*)(out + base + 160) = make_float2(oc + x23.x, od + x23.y);
        }
        __syncthreads();
    }
}

// ---------------- host launch ---------------------------------------------
extern "C" void kernel_launch(void* const* d_in, const int* in_sizes, int n_in,
                              void* d_out, int out_size) {
    (void)in_sizes; (void)n_in; (void)out_size;
    const float* x        = (const float*)d_in[0];
    const float* fusion_w = (const float*)d_in[1];
    const float* fusion_b = (const float*)d_in[2];
    const float* bn1_g    = (const float*)d_in[3];
    const float* bn1_b    = (const float*)d_in[4];
    const float* bn1_m    = (const float*)d_in[5];
    const float* bn1_v    = (const float*)d_in[6];
    const float* sa_w     = (const float*)d_in[7];
    const float* ca_w1    = (const float*)d_in[8];
    const float* ca_w2    = (const float*)d_in[9];
    const float* proj_w   = (const float*)d_in[10];
    const float* proj_b   = (const float*)d_in[11];
    const float* bn2_g    = (const float*)d_in[12];
    const float* bn2_b    = (const float*)d_in[13];
    const float* bn2_m    = (const float*)d_in[14];
    const float* bn2_v    = (const float*)d_in[15];
    float* out = (float*)d_out;

    prep1<<<(K1 * N1) / 256, 256>>>(fusion_w, fusion_b, bn1_g, bn1_b, bn1_m, bn1_v);
    prep2<<<(K2 * N2) / 256, 256>>>(proj_w, proj_b, bn2_g, bn2_b, bn2_m, bn2_v);
    gemm1<<<dim3(MTOT / 128, N1 / 128), 256>>>(x);
    spstats<<<MTOT / 8, 256>>>();
    spconv<<<MTOT / 256, 256>>>(sa_w);
    chstats_part<<<BQ * 8 * NSEG, 256>>>();
    chmlp<<<BQ, 256>>>(ca_w1, ca_w2);
    gemm2<<<dim3(MTOT / 128, N2 / 128), 256>>>(x, out);
}

// round 4
// speedup vs baseline: 2.6577x; 2.6577x over previous
#include <cuda_runtime.h>
#include <cstdint>

// ---------------- problem constants ----------------
#define BQ    8
#define HWQ   6400          // 80*80
#define MTOT  51200         // 8*6400
#define K1    1024
#define N1    256
#define K2    256
#define N2    1024
#define NSEG  25            // 6400 / 256

// ---------------- scratch (device globals) --------
__device__ __align__(16) float g_W1t[N1 * K1];        // [n][k] tf32-rounded (DWT+BN1 folded)
__device__ __align__(16) float g_bias1[N1];
__device__ __align__(16) float g_W2t[N2 * K2];        // [j][k] tf32-rounded, j = c'*4+g (permuted)
__device__ __align__(16) float g_bias2p[N2];
__device__ __align__(16) float g_fused[(long)MTOT * 256];
__device__ __align__(16) float g_sp_sum[2 * MTOT];    // per-ny partials
__device__ __align__(16) float g_sp_max[2 * MTOT];
__device__ __align__(16) float g_avg_sp[MTOT];
__device__ __align__(16) float g_max_sp[MTOT];
__device__ __align__(16) float g_gate[MTOT];
__device__ __align__(16) float g_chsum_part[NSEG * BQ * 256];
__device__ __align__(16) float g_chmax_part[NSEG * BQ * 256];
__device__ __align__(16) float g_chmap[BQ * 256];

// ---------------- PTX helpers ----------------------
__device__ __forceinline__ uint32_t smem_u32(const void* p) {
    uint32_t a;
    asm("{ .reg .u64 t; cvta.to.shared.u64 t, %1; cvt.u32.u64 %0, t; }" : "=r"(a) : "l"(p));
    return a;
}
__device__ __forceinline__ uint32_t tf32r(float f) {
    uint32_t u;
    asm("cvt.rna.tf32.f32 %0, %1;" : "=r"(u) : "f"(f));
    return u;
}
__device__ __forceinline__ void ldsm4(uint32_t* r, uint32_t addr) {
    asm volatile("ldmatrix.sync.aligned.m8n8.x4.shared.b16 {%0,%1,%2,%3}, [%4];"
                 : "=r"(r[0]), "=r"(r[1]), "=r"(r[2]), "=r"(r[3]) : "r"(addr));
}
__device__ __forceinline__ void mma8(float* d, const uint32_t* a, uint32_t b0, uint32_t b1) {
    asm volatile(
        "mma.sync.aligned.m16n8k8.row.col.f32.tf32.tf32.f32 "
        "{%0,%1,%2,%3}, {%4,%5,%6,%7}, {%8,%9}, {%0,%1,%2,%3};"
        : "+f"(d[0]), "+f"(d[1]), "+f"(d[2]), "+f"(d[3])
        : "r"(a[0]), "r"(a[1]), "r"(a[2]), "r"(a[3]), "r"(b0), "r"(b1));
}

// ---------------- K0a: prep fusion weights (fold DWT + BN1, [n][k], tf32) --
__global__ void prep1(const float* __restrict__ fw, const float* __restrict__ fb,
                      const float* __restrict__ g1, const float* __restrict__ b1,
                      const float* __restrict__ m1, const float* __restrict__ v1) {
    int idx = blockIdx.x * blockDim.x + threadIdx.x;
    if (idx >= K1 * N1) return;
    int o = idx & 255;
    int k = idx >> 8;            // k = c*4 + q, q = 2*dy + dx
    int c = k >> 2, q = k & 3;
    float inv = g1[o] * rsqrtf(v1[o] + 1e-5f);
    float slh = (q < 2) ? 1.f : -1.f;
    float shl = ((q & 1) == 0) ? 1.f : -1.f;
    float shh = slh * shl;
    float val = fw[o * 1024 + c]
              + slh * fw[o * 1024 + 256 + c]
              + shl * fw[o * 1024 + 512 + c]
              + shh * fw[o * 1024 + 768 + c];
    g_W1t[o * 1024 + k] = __uint_as_float(tf32r(0.5f * inv * val));
    if (k == 0) g_bias1[o] = fb[o] * inv + b1[o] - m1[o] * inv;
}

// ---------------- K0b: prep proj weights (fold BN2, permute, [j][k], tf32) -
__global__ void prep2(const float* __restrict__ pw, const float* __restrict__ pb,
                      const float* __restrict__ g2, const float* __restrict__ b2,
                      const float* __restrict__ m2, const float* __restrict__ v2) {
    int idx = blockIdx.x * blockDim.x + threadIdx.x;
    if (idx >= K2 * N2) return;
    int j = idx & 1023;          // j = c'*4 + g
    int k = idx >> 10;
    int o = (j & 3) * 256 + (j >> 2);
    float inv = g2[o] * rsqrtf(v2[o] + 1e-5f);
    g_W2t[j * 256 + k] = __uint_as_float(tf32r(pw[o * 256 + k] * inv));
    if (k == 0) g_bias2p[j] = pb[o] * inv + b2[o] - m2[o] * inv;
}

// ============================================================================
// GEMM1: mma.sync tf32. CTA 128m x 128n, k-chunk 32, double buffered.
// A[m][k=c*4+q] gathered from x (DWT), rounded to tf32. B = g_W1t slice.
// Epilogue: bias+relu -> g_fused; per-pixel channel sum/max partials.
// smem (bytes): A0@0, A1@18432, B0@36864, B1@55296, bias@73728(512),
//               redsum@74240(2048), redmax@76288(2048). total 78336.
// ============================================================================
#define G1_SMEM 78336
__global__ __launch_bounds__(512) void gemm1(const float* __restrict__ x) {
    extern __shared__ char smem[];
    const uint32_t sb = smem_u32(smem);
    const int tid = threadIdx.x;
    const int lane = tid & 31, warp = tid >> 5;
    const int wm = warp >> 2, wn = warp & 3;
    const int n0 = blockIdx.x * 128;
    const int m0 = blockIdx.y * 128;
    const int bb = m0 / HWQ;
    const int hw0 = m0 % HWQ;

    if (tid < 32) ((float4*)(smem + 73728))[tid] = ((const float4*)(g_bias1 + n0))[tid];

    // ---- A gather setup: idx = tid + i*512 -> c=(idx>>7), dy=(idx>>6)&1, mp=idx&63
    const int cA = tid >> 7;             // i=0 channel sub-index (0..3); i=1 adds 4
    const int dyA = (tid >> 6) & 1;
    const int mlA = (tid & 63) * 2;      // even local m -> even w, float4 never crosses rows
    const int hwA = hw0 + mlA;
    const int hA = hwA / 80, wA = hwA - hA * 80;
    const float* aPtr0 = x + (long)bb * 256 * 25600 + cA * 25600 + (2 * hA + dyA) * 160 + 2 * wA;
    const float* aPtr1 = aPtr0 + 4 * 25600;
    const int aStCol0 = (cA * 4 + dyA * 2) * 4;
    const int aStCol1 = ((cA + 4) * 4 + dyA * 2) * 4;

    // ---- B load setup
    const int nB = tid >> 3, kqB = tid & 7;
    const float* bPtr0 = g_W1t + (n0 + nB) * 1024 + kqB * 4;
    const float* bPtr1 = g_W1t + (n0 + nB + 64) * 1024 + kqB * 4;
    const int bStOff0 = nB * 144 + kqB * 16;
    const int bStOff1 = (nB + 64) * 144 + kqB * 16;

    // ---- ldmatrix lane address bases (pad 36 floats -> conflict-free)
    const int lrow = lane & 7, l8 = (lane >> 3) & 1, l16 = (lane >> 4) & 1;
    const uint32_t aLd = sb + (uint32_t)(((wm * 32 + lrow + l8 * 8) * 36 + l16 * 4) * 4);
    const uint32_t bLd = sb + 36864u + (uint32_t)(((wn * 32 + lrow + l16 * 8) * 36 + l8 * 4) * 4);

    float acc[2][4][4];
#pragma unroll
    for (int a = 0; a < 2; a++)
#pragma unroll
        for (int b = 0; b < 4; b++)
#pragma unroll
            for (int c = 0; c < 4; c++) acc[a][b][c] = 0.f;

    // prologue: chunk 0 into regs
    float4 aR0 = *(const float4*)aPtr0;
    float4 aR1 = *(const float4*)aPtr1;
    float4 bR0 = *(const float4*)bPtr0;
    float4 bR1 = *(const float4*)bPtr1;

    for (int it = 0; it < 32; ++it) {
        const int aOff = (it & 1) ? 18432 : 0;
        const int bOff = 36864 + aOff;
        // store current chunk
        {
            uint2 u;
            u.x = tf32r(aR0.x); u.y = tf32r(aR0.y);
            *(uint2*)(smem + aOff + mlA * 144 + aStCol0) = u;
            u.x = tf32r(aR0.z); u.y = tf32r(aR0.w);
            *(uint2*)(smem + aOff + (mlA + 1) * 144 + aStCol0) = u;
            u.x = tf32r(aR1.x); u.y = tf32r(aR1.y);
            *(uint2*)(smem + aOff + mlA * 144 + aStCol1) = u;
            u.x = tf32r(aR1.z); u.y = tf32r(aR1.w);
            *(uint2*)(smem + aOff + (mlA + 1) * 144 + aStCol1) = u;
            *(float4*)(smem + bOff + bStOff0) = bR0;
            *(float4*)(smem + bOff + bStOff1) = bR1;
        }
        __syncthreads();
        // prefetch next chunk
        if (it < 31) {
            aR0 = *(const float4*)(aPtr0 + (it + 1) * 204800);
            aR1 = *(const float4*)(aPtr1 + (it + 1) * 204800);
            bR0 = *(const float4*)(bPtr0 + (it + 1) * 32);
            bR1 = *(const float4*)(bPtr1 + (it + 1) * 32);
        }
        // compute
        const uint32_t aB = aLd + (uint32_t)aOff;
        const uint32_t bB = bLd + (uint32_t)aOff;
#pragma unroll
        for (int k8 = 0; k8 < 4; ++k8) {
            uint32_t af[2][4], bf[2][4];
            ldsm4(af[0], aB + k8 * 32);
            ldsm4(af[1], aB + k8 * 32 + 16 * 144);
            ldsm4(bf[0], bB + k8 * 32);
            ldsm4(bf[1], bB + k8 * 32 + 16 * 144);
#pragma unroll
            for (int ms = 0; ms < 2; ++ms) {
                mma8(acc[ms][0], af[ms], bf[0][0], bf[0][1]);
                mma8(acc[ms][1], af[ms], bf[0][2], bf[0][3]);
                mma8(acc[ms][2], af[ms], bf[1][0], bf[1][1]);
                mma8(acc[ms][3], af[ms], bf[1][2], bf[1][3]);
            }
        }
    }
    __syncthreads();

    // ---- epilogue: bias+relu -> g_fused, row sum/max partial reduction
    const float* biasS = (const float*)(smem + 73728);
    float* redS = (float*)(smem + 74240);
    float* redM = (float*)(smem + 76288);
    float rs[2][2] = {{0.f, 0.f}, {0.f, 0.f}};
    float rm[2][2] = {{0.f, 0.f}, {0.f, 0.f}};
#pragma unroll
    for (int ms = 0; ms < 2; ++ms) {
        int row0 = m0 + wm * 32 + ms * 16 + (lane >> 2);
#pragma unroll
        for (int ns = 0; ns < 4; ++ns) {
            int col = wn * 32 + ns * 8 + (lane & 3) * 2;
            float b0 = biasS[col], b1 = biasS[col + 1];
            float v0 = fmaxf(acc[ms][ns][0] + b0, 0.f);
            float v1 = fmaxf(acc[ms][ns][1] + b1, 0.f);
            *(float2*)(g_fused + (long)row0 * 256 + n0 + col) = make_float2(v0, v1);
            rs[ms][0] += v0 + v1;
            rm[ms][0] = fmaxf(rm[ms][0], fmaxf(v0, v1));
            float v2 = fmaxf(acc[ms][ns][2] + b0, 0.f);
            float v3 = fmaxf(acc[ms][ns][3] + b1, 0.f);
            *(float2*)(g_fused + (long)(row0 + 8) * 256 + n0 + col) = make_float2(v2, v3);
            rs[ms][1] += v2 + v3;
            rm[ms][1] = fmaxf(rm[ms][1], fmaxf(v2, v3));
        }
    }
#pragma unroll
    for (int ms = 0; ms < 2; ++ms)
#pragma unroll
        for (int hf = 0; hf < 2; ++hf) {
            float s = rs[ms][hf], mx = rm[ms][hf];
            s += __shfl_xor_sync(0xffffffffu, s, 1);
            s += __shfl_xor_sync(0xffffffffu, s, 2);
            mx = fmaxf(mx, __shfl_xor_sync(0xffffffffu, mx, 1));
            mx = fmaxf(mx, __shfl_xor_sync(0xffffffffu, mx, 2));
            if ((lane & 3) == 0) {
                int r_l = wm * 32 + ms * 16 + (lane >> 2) + hf * 8;
                redS[r_l * 4 + wn] = s;
                redM[r_l * 4 + wn] = mx;
            }
        }
    __syncthreads();
    if (tid < 128) {
        float s = redS[tid * 4] + redS[tid * 4 + 1] + redS[tid * 4 + 2] + redS[tid * 4 + 3];
        float mx = fmaxf(fmaxf(redM[tid * 4], redM[tid * 4 + 1]),
                         fmaxf(redM[tid * 4 + 2], redM[tid * 4 + 3]));
        g_sp_sum[blockIdx.x * MTOT + m0 + tid] = s;
        g_sp_max[blockIdx.x * MTOT + m0 + tid] = mx;
    }
}

// ---------------- spfin: combine the two n-half partials -------------------
__global__ void spfin() {
    int m = blockIdx.x * 256 + threadIdx.x;
    g_avg_sp[m] = (g_sp_sum[m] + g_sp_sum[MTOT + m]) * (1.f / 256.f);
    g_max_sp[m] = fmaxf(g_sp_max[m], g_sp_max[MTOT + m]);
}

// ---------------- spconv: 7x7 spatial conv + sigmoid -----------------------
__global__ void spconv(const float* __restrict__ sa_w) {
    __shared__ float sw[98];
    if (threadIdx.x < 98) sw[threadIdx.x] = sa_w[threadIdx.x];
    __syncthreads();
    int m = blockIdx.x * 256 + threadIdx.x;
    int bb = m / HWQ, hw = m % HWQ;
    int h = hw / 80, w = hw % 80;
    float acc = 0.f;
#pragma unroll
    for (int ky = 0; ky < 7; ky++) {
        int y = h + ky - 3;
        if ((unsigned)y < 80u) {
#pragma unroll
            for (int kx = 0; kx < 7; kx++) {
                int xx = w + kx - 3;
                if ((unsigned)xx < 80u) {
                    int mi = bb * HWQ + y * 80 + xx;
                    acc += g_avg_sp[mi] * sw[ky * 7 + kx]
                         + g_max_sp[mi] * sw[49 + ky * 7 + kx];
                }
            }
        }
    }
    g_gate[m] = 1.f / (1.f + expf(-acc));
}

// ---------------- chstats: per-(b,c) sum/max of gate*fused, partials -------
__global__ void chstats_part() {
    int bid = blockIdx.x;                 // 8*8*25 = 1600
    int bb = bid / 200;
    int rem = bid % 200;
    int cg = rem / NSEG;
    int seg = rem % NSEG;
    int cl = threadIdx.x & 31;
    int r0 = threadIdx.x >> 5;
    int c = cg * 32 + cl;
    float s = 0.f, mx = 0.f;
    for (int r = r0; r < 256; r += 8) {
        int m = bb * HWQ + seg * 256 + r;
        float v = g_gate[m] * g_fused[(long)m * 256 + c];
        s += v;
        mx = fmaxf(mx, v);
    }
    __shared__ float ss[256], sm_[256];
    ss[threadIdx.x] = s;
    sm_[threadIdx.x] = mx;
    __syncthreads();
    if (r0 == 0) {
#pragma unroll
        for (int r = 1; r < 8; r++) {
            s += ss[r * 32 + cl];
            mx = fmaxf(mx, sm_[r * 32 + cl]);
        }
        g_chsum_part[(seg * BQ + bb) * 256 + c] = s;
        g_chmax_part[(seg * BQ + bb) * 256 + c] = mx;
    }
}

// ---------------- chmlp: finalize stats + channel MLP + sigmoid ------------
__global__ void chmlp(const float* __restrict__ w1, const float* __restrict__ w2) {
    int bb = blockIdx.x;
    int tid = threadIdx.x;
    __shared__ float sA[256], sM[256], sH[32];
    float s = 0.f, mx = 0.f;
    for (int seg = 0; seg < NSEG; seg++) {
        s += g_chsum_part[(seg * BQ + bb) * 256 + tid];
        mx = fmaxf(mx, g_chmax_part[(seg * BQ + bb) * 256 + tid]);
    }
    sA[tid] = s * (1.f / 6400.f);
    sM[tid] = mx;
    __syncthreads();
    int warp = tid >> 5, lane = tid & 31;
#pragma unroll
    for (int it = 0; it < 4; it++) {
        int t = warp * 4 + it;            // 0..31
        int u = t & 15, which = t >> 4;
        const float* vec = which ? sM : sA;
        float d = 0.f;
        for (int cc = lane; cc < 256; cc += 32) d += w1[u * 256 + cc] * vec[cc];
#pragma unroll
        for (int off = 16; off; off >>= 1) d += __shfl_xor_sync(0xffffffffu, d, off);
        if (lane == 0) sH[t] = fmaxf(d, 0.f);
    }
    __syncthreads();
    float o = 0.f;
#pragma unroll
    for (int u = 0; u < 16; u++) o += w2[tid * 16 + u] * (sH[u] + sH[16 + u]);
    g_chmap[bb * 256 + tid] = 1.f / (1.f + expf(-o));
}

// ============================================================================
// GEMM2: mma.sync tf32. Full-K A tile (gated, tf32) resident in smem;
// 8 internal n-blocks of 128 with k-chunked double-buffered B (L2-resident).
// Epilogue: bias+relu -> iDWT (shfl pair exchange) -> +identity -> out.
// smem: A@0 (128x260x4 = 133120), B0@133120, B1@151552, bias@169984(4096),
//       cmap@174080(1024), gate@175104(512). total 175616.
// ============================================================================
#define G2_SMEM 175616
__global__ __launch_bounds__(512) void gemm2(const float* __restrict__ x,
                                             float* __restrict__ out) {
    extern __shared__ char smem[];
    const uint32_t sb = smem_u32(smem);
    const int tid = threadIdx.x;
    const int lane = tid & 31, warp = tid >> 5;
    const int wm = warp >> 2, wn = warp & 3;
    const int m0 = blockIdx.x * 128;
    const int bb = m0 / HWQ;
    const int hw0 = m0 % HWQ;

    float* biasS = (float*)(smem + 169984);
    float* cmapS = (float*)(smem + 174080);
    float* gateS = (float*)(smem + 175104);
    if (tid < 256) ((float4*)biasS)[tid] = ((const float4*)g_bias2p)[tid];
    if (tid < 64) ((float4*)cmapS)[tid] = ((const float4*)(g_chmap + bb * 256))[tid];
    if (tid < 32) ((float4*)gateS)[tid] = ((const float4*)(g_gate + m0))[tid];
    __syncthreads();

    // ---- fill full-K A tile: fused * gate * cmap, tf32-rounded
    const int kqA = tid & 63;
    const int ml0 = tid >> 6;
#pragma unroll
    for (int i = 0; i < 16; ++i) {
        int m_l = ml0 + i * 8;
        float4 v = *(const float4*)(g_fused + (long)(m0 + m_l) * 256 + kqA * 4);
        float gm = gateS[m_l];
        v.x *= gm * cmapS[kqA * 4 + 0];
        v.y *= gm * cmapS[kqA * 4 + 1];
        v.z *= gm * cmapS[kqA * 4 + 2];
        v.w *= gm * cmapS[kqA * 4 + 3];
        uint4 u;
        u.x = tf32r(v.x); u.y = tf32r(v.y); u.z = tf32r(v.z); u.w = tf32r(v.w);
        *(uint4*)(smem + (m_l * 260 + kqA * 4) * 4) = u;
    }

    const int nB = tid >> 3, kqB = tid & 7;
    const int bStOff0 = nB * 144 + kqB * 16;
    const int bStOff1 = (nB + 64) * 144 + kqB * 16;

    const int lrow = lane & 7, l8 = (lane >> 3) & 1, l16 = (lane >> 4) & 1;
    const uint32_t aLd = sb + (uint32_t)(((wm * 32 + lrow + l8 * 8) * 260 + l16 * 4) * 4);
    const uint32_t bLdOff = (uint32_t)(((wn * 32 + lrow + l16 * 8) * 36 + l8 * 4) * 4);

    for (int nb = 0; nb < 8; ++nb) {
        float acc[2][4][4];
#pragma unroll
        for (int a = 0; a < 2; a++)
#pragma unroll
            for (int b = 0; b < 4; b++)
#pragma unroll
                for (int c = 0; c < 4; c++) acc[a][b][c] = 0.f;

        const float* bPtr0 = g_W2t + (nb * 128 + nB) * 256 + kqB * 4;
        const float* bPtr1 = bPtr0 + 64 * 256;
        float4 bR0 = *(const float4*)bPtr0;
        float4 bR1 = *(const float4*)bPtr1;

        for (int kc = 0; kc < 8; ++kc) {
            const int bOff = 133120 + ((kc & 1) ? 18432 : 0);
            *(float4*)(smem + bOff + bStOff0) = bR0;
            *(float4*)(smem + bOff + bStOff1) = bR1;
            __syncthreads();
            if (kc < 7) {
                bR0 = *(const float4*)(bPtr0 + (kc + 1) * 32);
                bR1 = *(const float4*)(bPtr1 + (kc + 1) * 32);
            }
            const uint32_t bB = sb + (uint32_t)bOff + bLdOff;
#pragma unroll
            for (int k8 = 0; k8 < 4; ++k8) {
                uint32_t af[2][4], bf[2][4];
                ldsm4(af[0], aLd + (kc * 32 + k8 * 8) * 4);
                ldsm4(af[1], aLd + (kc * 32 + k8 * 8) * 4 + 16 * 1040);
                ldsm4(bf[0], bB + k8 * 32);
                ldsm4(bf[1], bB + k8 * 32 + 16 * 144);
#pragma unroll
                for (int ms = 0; ms < 2; ++ms) {
                    mma8(acc[ms][0], af[ms], bf[0][0], bf[0][1]);
                    mma8(acc[ms][1], af[ms], bf[0][2], bf[0][3]);
                    mma8(acc[ms][2], af[ms], bf[1][0], bf[1][1]);
                    mma8(acc[ms][3], af[ms], bf[1][2], bf[1][3]);
                }
            }
        }

        // ---- epilogue for this n-block: bias+relu -> iDWT -> +identity
#pragma unroll
        for (int ms = 0; ms < 2; ++ms) {
#pragma unroll
            for (int hf = 0; hf < 2; ++hf) {
                int m_l = wm * 32 + ms * 16 + (lane >> 2) + hf * 8;
                int hw = hw0 + m_l;
                int h = hw / 80, w = hw - h * 80;
#pragma unroll
                for (int ns = 0; ns < 4; ++ns) {
                    int jc = nb * 128 + wn * 32 + ns * 8 + (lane & 3) * 2;
                    float v0 = fmaxf(acc[ms][ns][hf * 2 + 0] + biasS[jc], 0.f);
                    float v1 = fmaxf(acc[ms][ns][hf * 2 + 1] + biasS[jc + 1], 0.f);
                    // laneE(v0,v1)=(ll,lh); laneO(v0,v1)=(hl,hh)
                    float p = v0 + v1;      // laneE: ll+lh   laneO: hl+hh
                    float r = v0 - v1;      // laneE: ll-lh   laneO: hl-hh
                    float op = __shfl_xor_sync(0xffffffffu, p, 1);
                    float orr = __shfl_xor_sync(0xffffffffu, r, 1);
                    float e0, e1;
                    if (lane & 1) {         // bottom row: oc, od
                        e0 = 0.5f * (orr + r);
                        e1 = 0.5f * (orr - r);
                    } else {                // top row: oa, ob
                        e0 = 0.5f * (p + op);
                        e1 = 0.5f * (p - op);
                    }
                    int cp = jc >> 2;       // output channel
                    long base = (((long)bb * 256 + cp) * 160 + 2 * h + (lane & 1)) * 160 + 2 * w;
                    float2 xi = *(const float2*)(x + base);
                    *(float2*)(out + base) = make_float2(e0 + xi.x, e1 + xi.y);
                }
            }
        }
    }
}

// ---------------- host launch ---------------------------------------------
extern "C" void kernel_launch(void* const* d_in, const int* in_sizes, int n_in,
                              void* d_out, int out_size) {
    (void)in_sizes; (void)n_in; (void)out_size;
    const float* x        = (const float*)d_in[0];
    const float* fusion_w = (const float*)d_in[1];
    const float* fusion_b = (const float*)d_in[2];
    const float* bn1_g    = (const float*)d_in[3];
    const float* bn1_b    = (const float*)d_in[4];
    const float* bn1_m    = (const float*)d_in[5];
    const float* bn1_v    = (const float*)d_in[6];
    const float* sa_w     = (const float*)d_in[7];
    const float* ca_w1    = (const float*)d_in[8];
    const float* ca_w2    = (const float*)d_in[9];
    const float* proj_w   = (const float*)d_in[10];
    const float* proj_b   = (const float*)d_in[11];
    const float* bn2_g    = (const float*)d_in[12];
    const float* bn2_b    = (const float*)d_in[13];
    const float* bn2_m    = (const float*)d_in[14];
    const float* bn2_v    = (const float*)d_in[15];
    float* out = (float*)d_out;

    cudaFuncSetAttribute(gemm1, cudaFuncAttributeMaxDynamicSharedMemorySize, G1_SMEM);
    cudaFuncSetAttribute(gemm2, cudaFuncAttributeMaxDynamicSharedMemorySize, G2_SMEM);

    prep1<<<(K1 * N1) / 256, 256>>>(fusion_w, fusion_b, bn1_g, bn1_b, bn1_m, bn1_v);
    prep2<<<(K2 * N2) / 256, 256>>>(proj_w, proj_b, bn2_g, bn2_b, bn2_m, bn2_v);
    gemm1<<<dim3(2, 400), 512, G1_SMEM>>>(x);
    spfin<<<MTOT / 256, 256>>>();
    spconv<<<MTOT / 256, 256>>>(sa_w);
    chstats_part<<<BQ * 8 * NSEG, 256>>>();
    chmlp<<<BQ, 256>>>(ca_w1, ca_w2);
    gemm2<<<MTOT / 128, 512, G2_SMEM>>>(x, out);
}

// round 5
// speedup vs baseline: 2.8315x; 1.0654x over previous
#include <cuda_runtime.h>
#include <cstdint>

// ---------------- problem constants ----------------
#define BQ    8
#define HWQ   6400          // 80*80
#define MTOT  51200         // 8*6400
#define K1    1024
#define N1    256
#define K2    256
#define N2    1024
#define NSEG  25            // 6400 / 256

// ---------------- scratch (device globals) --------
__device__ __align__(16) float g_W1t[N1 * K1];        // [n][k] tf32-rounded (DWT+BN1 folded)
__device__ __align__(16) float g_bias1[N1];
__device__ __align__(16) float g_W2t[N2 * K2];        // [j][k] tf32-rounded, j = c'*4+g (permuted)
__device__ __align__(16) float g_bias2p[N2];
__device__ __align__(16) float g_fused[(long)MTOT * 256];
__device__ __align__(16) float g_avg_sp[MTOT];
__device__ __align__(16) float g_max_sp[MTOT];
__device__ __align__(16) float g_gate[MTOT];
__device__ __align__(16) float g_chsum_part[NSEG * BQ * 256];
__device__ __align__(16) float g_chmax_part[NSEG * BQ * 256];
__device__ __align__(16) float g_chmap[BQ * 256];

// ---------------- PTX helpers ----------------------
__device__ __forceinline__ uint32_t smem_u32(const void* p) {
    uint32_t a;
    asm("{ .reg .u64 t; cvta.to.shared.u64 t, %1; cvt.u32.u64 %0, t; }" : "=r"(a) : "l"(p));
    return a;
}
__device__ __forceinline__ uint32_t tf32r(float f) {
    uint32_t u;
    asm("cvt.rna.tf32.f32 %0, %1;" : "=r"(u) : "f"(f));
    return u;
}
__device__ __forceinline__ void ldsm4(uint32_t* r, uint32_t addr) {
    asm volatile("ldmatrix.sync.aligned.m8n8.x4.shared.b16 {%0,%1,%2,%3}, [%4];"
                 : "=r"(r[0]), "=r"(r[1]), "=r"(r[2]), "=r"(r[3]) : "r"(addr));
}
__device__ __forceinline__ void mma8(float* d, const uint32_t* a, uint32_t b0, uint32_t b1) {
    asm volatile(
        "mma.sync.aligned.m16n8k8.row.col.f32.tf32.tf32.f32 "
        "{%0,%1,%2,%3}, {%4,%5,%6,%7}, {%8,%9}, {%0,%1,%2,%3};"
        : "+f"(d[0]), "+f"(d[1]), "+f"(d[2]), "+f"(d[3])
        : "r"(a[0]), "r"(a[1]), "r"(a[2]), "r"(a[3]), "r"(b0), "r"(b1));
}
__device__ __forceinline__ void cpa16(uint32_t dst, const void* src) {
    asm volatile("cp.async.cg.shared.global [%0], [%1], 16;" :: "r"(dst), "l"(src));
}
#define CP_COMMIT asm volatile("cp.async.commit_group;" ::: "memory")
#define CP_WAIT1  asm volatile("cp.async.wait_group 1;" ::: "memory")
#define CP_WAIT0  asm volatile("cp.async.wait_group 0;" ::: "memory")

// ---------------- prep: fold DWT+BN1 into W1 [n][k]; BN2+permute into W2 [j][k]
__global__ void prep(const float* __restrict__ fw, const float* __restrict__ fb,
                     const float* __restrict__ g1, const float* __restrict__ b1,
                     const float* __restrict__ m1, const float* __restrict__ v1,
                     const float* __restrict__ pw, const float* __restrict__ pb,
                     const float* __restrict__ g2, const float* __restrict__ b2,
                     const float* __restrict__ m2, const float* __restrict__ v2) {
    int idx = blockIdx.x * blockDim.x + threadIdx.x;
    if (idx < K1 * N1) {
        int o = idx & 255;
        int k = idx >> 8;            // k = c*4 + q, q = 2*dy + dx
        int c = k >> 2, q = k & 3;
        float inv = g1[o] * rsqrtf(v1[o] + 1e-5f);
        float slh = (q < 2) ? 1.f : -1.f;
        float shl = ((q & 1) == 0) ? 1.f : -1.f;
        float shh = slh * shl;
        float val = fw[o * 1024 + c]
                  + slh * fw[o * 1024 + 256 + c]
                  + shl * fw[o * 1024 + 512 + c]
                  + shh * fw[o * 1024 + 768 + c];
        g_W1t[o * 1024 + k] = __uint_as_float(tf32r(0.5f * inv * val));
        if (k == 0) g_bias1[o] = fb[o] * inv + b1[o] - m1[o] * inv;
    } else {
        int idx2 = idx - K1 * N1;
        int j = idx2 & 1023;          // j = c'*4 + g
        int k = idx2 >> 10;
        int o = (j & 3) * 256 + (j >> 2);
        float inv = g2[o] * rsqrtf(v2[o] + 1e-5f);
        g_W2t[j * 256 + k] = __uint_as_float(tf32r(pw[o * 256 + k] * inv));
        if (k == 0) g_bias2p[j] = pb[o] * inv + b2[o] - m2[o] * inv;
    }
}

// ============================================================================
// GEMM1: CTA 128m x 256n (full N), 16 warps 4m x 4n, warp tile 32x64.
// A: DWT gather from x, cvt.rna.tf32, STS (reg-prefetched). B: cp.async.
// Epilogue: bias+relu -> g_fused; full per-pixel channel sum/max -> g_avg/g_max.
// smem: A0@0(18432) A1@18432 B0@36864(36864) B1@73728 bias@110592(1024)
//       redS@111616(2048) redM@113664(2048)  total 115712
// ============================================================================
#define G1_SMEM 115712
__global__ __launch_bounds__(512) void gemm1(const float* __restrict__ x) {
    extern __shared__ char smem[];
    const uint32_t sb = smem_u32(smem);
    const int tid = threadIdx.x;
    const int lane = tid & 31, warp = tid >> 5;
    const int wm = warp & 3, wn = warp >> 2;
    const int m0 = blockIdx.x * 128;
    const int bb = m0 / HWQ;
    const int hw0 = m0 % HWQ;

    if (tid < 64) ((float4*)(smem + 110592))[tid] = ((const float4*)g_bias1)[tid];

    // ---- A gather setup (chunk ch covers channels ch*8 .. ch*8+7)
    const int cA = tid >> 7;             // 0..3 (+4 for second float4)
    const int dyA = (tid >> 6) & 1;
    const int mlA = (tid & 63) * 2;
    const int hwA = hw0 + mlA;
    const int hA = hwA / 80, wA = hwA - hA * 80;
    const float* aPtr0 = x + (long)bb * 256 * 25600 + cA * 25600 + (2 * hA + dyA) * 160 + 2 * wA;
    const float* aPtr1 = aPtr0 + 4 * 25600;
    const int aStCol0 = (cA * 4 + dyA * 2) * 4;          // byte col
    const int aStCol1 = ((cA + 4) * 4 + dyA * 2) * 4;

    // ---- B cp.async setup: 256 rows x 32 floats per chunk
    const int rowB = tid >> 1;
    const int colF = (tid & 1) * 16;     // float offset in row
    const float* bSrcBase = g_W1t + rowB * 1024 + colF;
    const uint32_t bDstOff = (uint32_t)(rowB * 144 + colF * 4);

    // ---- ldsm lane bases (pad 36 floats/row)
    const int lrow = lane & 7, l8 = (lane >> 3) & 1, l16 = (lane >> 4) & 1;
    const uint32_t aLd = sb + (uint32_t)(((wm * 32 + lrow + l8 * 8) * 36 + l16 * 4) * 4);
    const uint32_t bLd = sb + 36864u + (uint32_t)(((wn * 64 + lrow + l16 * 8) * 36 + l8 * 4) * 4);

    float acc[2][8][4];
#pragma unroll
    for (int a = 0; a < 2; a++)
#pragma unroll
        for (int b = 0; b < 8; b++)
#pragma unroll
            for (int c = 0; c < 4; c++) acc[a][b][c] = 0.f;

    // prologue: issue B(0), prefetch A(0) into regs
    {
        uint32_t bD = sb + 36864u + bDstOff;
        const float* bS = bSrcBase;
        cpa16(bD, bS); cpa16(bD + 16, bS + 4); cpa16(bD + 32, bS + 8); cpa16(bD + 48, bS + 12);
        CP_COMMIT;
    }
    float4 aR0 = *(const float4*)aPtr0;
    float4 aR1 = *(const float4*)aPtr1;

    for (int it = 0; it < 32; ++it) {
        const uint32_t aOff = (it & 1) ? 18432u : 0u;
        const uint32_t bOff = 36864u + ((it & 1) ? 36864u : 0u);
        if (it < 31) {  // issue B(it+1) into other buffer (freed by trailing sync of it-1)
            uint32_t bD = sb + 36864u + (((it + 1) & 1) ? 36864u : 0u) + bDstOff;
            const float* bS = bSrcBase + (it + 1) * 32;
            cpa16(bD, bS); cpa16(bD + 16, bS + 4); cpa16(bD + 32, bS + 8); cpa16(bD + 48, bS + 12);
            CP_COMMIT;
        }
        // STS A(it) from regs
        {
            uint2 u;
            u.x = tf32r(aR0.x); u.y = tf32r(aR0.y);
            *(uint2*)(smem + aOff + mlA * 144 + aStCol0) = u;
            u.x = tf32r(aR0.z); u.y = tf32r(aR0.w);
            *(uint2*)(smem + aOff + (mlA + 1) * 144 + aStCol0) = u;
            u.x = tf32r(aR1.x); u.y = tf32r(aR1.y);
            *(uint2*)(smem + aOff + mlA * 144 + aStCol1) = u;
            u.x = tf32r(aR1.z); u.y = tf32r(aR1.w);
            *(uint2*)(smem + aOff + (mlA + 1) * 144 + aStCol1) = u;
        }
        if (it < 31) { CP_WAIT1; } else { CP_WAIT0; }
        __syncthreads();
        if (it < 31) {  // prefetch next A
            aR0 = *(const float4*)(aPtr0 + (it + 1) * 204800);
            aR1 = *(const float4*)(aPtr1 + (it + 1) * 204800);
        }
        const uint32_t aB = aLd + aOff;
        const uint32_t bB = bLd + (bOff - 36864u);
#pragma unroll
        for (int k8 = 0; k8 < 4; ++k8) {
            uint32_t af[2][4], bf[4][4];
            ldsm4(af[0], aB + k8 * 32);
            ldsm4(af[1], aB + k8 * 32 + 16 * 144);
#pragma unroll
            for (int i = 0; i < 4; ++i) ldsm4(bf[i], bB + k8 * 32 + i * 16 * 144);
#pragma unroll
            for (int ms = 0; ms < 2; ++ms)
#pragma unroll
                for (int i = 0; i < 4; ++i) {
                    mma8(acc[ms][2 * i + 0], af[ms], bf[i][0], bf[i][1]);
                    mma8(acc[ms][2 * i + 1], af[ms], bf[i][2], bf[i][3]);
                }
        }
        __syncthreads();
    }

    // ---- epilogue: bias+relu -> g_fused; full-row sum/max
    const float* biasS = (const float*)(smem + 110592);
    float* redS = (float*)(smem + 111616);
    float* redM = (float*)(smem + 113664);
    float rs[2][2] = {{0.f, 0.f}, {0.f, 0.f}};
    float rm[2][2] = {{0.f, 0.f}, {0.f, 0.f}};
#pragma unroll
    for (int ms = 0; ms < 2; ++ms) {
        int row0 = m0 + wm * 32 + ms * 16 + (lane >> 2);
#pragma unroll
        for (int ns = 0; ns < 8; ++ns) {
            int col = wn * 64 + ns * 8 + (lane & 3) * 2;
            float b0 = biasS[col], b1 = biasS[col + 1];
            float v0 = fmaxf(acc[ms][ns][0] + b0, 0.f);
            float v1 = fmaxf(acc[ms][ns][1] + b1, 0.f);
            *(float2*)(g_fused + (long)row0 * 256 + col) = make_float2(v0, v1);
            rs[ms][0] += v0 + v1;
            rm[ms][0] = fmaxf(rm[ms][0], fmaxf(v0, v1));
            float v2 = fmaxf(acc[ms][ns][2] + b0, 0.f);
            float v3 = fmaxf(acc[ms][ns][3] + b1, 0.f);
            *(float2*)(g_fused + (long)(row0 + 8) * 256 + col) = make_float2(v2, v3);
            rs[ms][1] += v2 + v3;
            rm[ms][1] = fmaxf(rm[ms][1], fmaxf(v2, v3));
        }
    }
#pragma unroll
    for (int ms = 0; ms < 2; ++ms)
#pragma unroll
        for (int hf = 0; hf < 2; ++hf) {
            float s = rs[ms][hf], mx = rm[ms][hf];
            s += __shfl_xor_sync(0xffffffffu, s, 1);
            s += __shfl_xor_sync(0xffffffffu, s, 2);
            mx = fmaxf(mx, __shfl_xor_sync(0xffffffffu, mx, 1));
            mx = fmaxf(mx, __shfl_xor_sync(0xffffffffu, mx, 2));
            if ((lane & 3) == 0) {
                int r_l = wm * 32 + ms * 16 + (lane >> 2) + hf * 8;
                redS[r_l * 4 + wn] = s;
                redM[r_l * 4 + wn] = mx;
            }
        }
    __syncthreads();
    if (tid < 128) {
        float s = redS[tid * 4] + redS[tid * 4 + 1] + redS[tid * 4 + 2] + redS[tid * 4 + 3];
        float mx = fmaxf(fmaxf(redM[tid * 4], redM[tid * 4 + 1]),
                         fmaxf(redM[tid * 4 + 2], redM[tid * 4 + 3]));
        g_avg_sp[m0 + tid] = s * (1.f / 256.f);
        g_max_sp[m0 + tid] = mx;
    }
}

// ---------------- spconv: 7x7 spatial conv + sigmoid -----------------------
__global__ void spconv(const float* __restrict__ sa_w) {
    __shared__ float sw[98];
    if (threadIdx.x < 98) sw[threadIdx.x] = sa_w[threadIdx.x];
    __syncthreads();
    int m = blockIdx.x * 256 + threadIdx.x;
    int bb = m / HWQ, hw = m % HWQ;
    int h = hw / 80, w = hw % 80;
    float acc = 0.f;
#pragma unroll
    for (int ky = 0; ky < 7; ky++) {
        int y = h + ky - 3;
        if ((unsigned)y < 80u) {
#pragma unroll
            for (int kx = 0; kx < 7; kx++) {
                int xx = w + kx - 3;
                if ((unsigned)xx < 80u) {
                    int mi = bb * HWQ + y * 80 + xx;
                    acc += g_avg_sp[mi] * sw[ky * 7 + kx]
                         + g_max_sp[mi] * sw[49 + ky * 7 + kx];
                }
            }
        }
    }
    g_gate[m] = 1.f / (1.f + expf(-acc));
}

// ---------------- chstats: per-(b,c) sum/max of gate*fused, partials -------
__global__ void chstats_part() {
    int bid = blockIdx.x;                 // 8*8*25 = 1600
    int bb = bid / 200;
    int rem = bid % 200;
    int cg = rem / NSEG;
    int seg = rem % NSEG;
    int cl = threadIdx.x & 31;
    int r0 = threadIdx.x >> 5;
    int c = cg * 32 + cl;
    float s = 0.f, mx = 0.f;
    for (int r = r0; r < 256; r += 8) {
        int m = bb * HWQ + seg * 256 + r;
        float v = g_gate[m] * g_fused[(long)m * 256 + c];
        s += v;
        mx = fmaxf(mx, v);
    }
    __shared__ float ss[256], sm_[256];
    ss[threadIdx.x] = s;
    sm_[threadIdx.x] = mx;
    __syncthreads();
    if (r0 == 0) {
#pragma unroll
        for (int r = 1; r < 8; r++) {
            s += ss[r * 32 + cl];
            mx = fmaxf(mx, sm_[r * 32 + cl]);
        }
        g_chsum_part[(seg * BQ + bb) * 256 + c] = s;
        g_chmax_part[(seg * BQ + bb) * 256 + c] = mx;
    }
}

// ---------------- chmlp: finalize stats + channel MLP + sigmoid ------------
__global__ void chmlp(const float* __restrict__ w1, const float* __restrict__ w2) {
    int bb = blockIdx.x;
    int tid = threadIdx.x;
    __shared__ float sA[256], sM[256], sH[32];
    float s = 0.f, mx = 0.f;
    for (int seg = 0; seg < NSEG; seg++) {
        s += g_chsum_part[(seg * BQ + bb) * 256 + tid];
        mx = fmaxf(mx, g_chmax_part[(seg * BQ + bb) * 256 + tid]);
    }
    sA[tid] = s * (1.f / 6400.f);
    sM[tid] = mx;
    __syncthreads();
    int warp = tid >> 5, lane = tid & 31;
#pragma unroll
    for (int it = 0; it < 4; it++) {
        int t = warp * 4 + it;            // 0..31
        int u = t & 15, which = t >> 4;
        const float* vec = which ? sM : sA;
        float d = 0.f;
        for (int cc = lane; cc < 256; cc += 32) d += w1[u * 256 + cc] * vec[cc];
#pragma unroll
        for (int off = 16; off; off >>= 1) d += __shfl_xor_sync(0xffffffffu, d, off);
        if (lane == 0) sH[t] = fmaxf(d, 0.f);
    }
    __syncthreads();
    float o = 0.f;
#pragma unroll
    for (int u = 0; u < 16; u++) o += w2[tid * 16 + u] * (sH[u] + sH[16 + u]);
    g_chmap[bb * 256 + tid] = 1.f / (1.f + expf(-o));
}

// ============================================================================
// GEMM2: full-K gated A tile resident (128x260f). 4 n-blocks of 256, B via
// cp.async double buffer. Warp tile 32x64. Epilogue: bias+relu -> iDWT
// (shfl pair exchange) -> +identity -> out; overlaps next B prefetch.
// smem: A@0(133120) B0@133120(36864) B1@169984 bias@206848(4096)
//       cmap@210944(1024) gate@211968(512)  total 212480
// ============================================================================
#define G2_SMEM 212480
__global__ __launch_bounds__(512) void gemm2(const float* __restrict__ x,
                                             float* __restrict__ out) {
    extern __shared__ char smem[];
    const uint32_t sb = smem_u32(smem);
    const int tid = threadIdx.x;
    const int lane = tid & 31, warp = tid >> 5;
    const int wm = warp & 3, wn = warp >> 2;
    const int m0 = blockIdx.x * 128;
    const int bb = m0 / HWQ;
    const int hw0 = m0 % HWQ;

    float* biasS = (float*)(smem + 206848);
    float* cmapS = (float*)(smem + 210944);
    float* gateS = (float*)(smem + 211968);
    if (tid < 256) ((float4*)biasS)[tid] = ((const float4*)g_bias2p)[tid];
    if (tid < 64) ((float4*)cmapS)[tid] = ((const float4*)(g_chmap + bb * 256))[tid];
    if (tid < 32) ((float4*)gateS)[tid] = ((const float4*)(g_gate + m0))[tid];
    __syncthreads();

    // ---- fill full-K A tile: fused * gate * cmap, tf32-rounded (pad 260)
    const int kqA = tid & 63;
    const int ml0 = tid >> 6;
#pragma unroll
    for (int i = 0; i < 16; ++i) {
        int m_l = ml0 + i * 8;
        float4 v = *(const float4*)(g_fused + (long)(m0 + m_l) * 256 + kqA * 4);
        float gm = gateS[m_l];
        v.x *= gm * cmapS[kqA * 4 + 0];
        v.y *= gm * cmapS[kqA * 4 + 1];
        v.z *= gm * cmapS[kqA * 4 + 2];
        v.w *= gm * cmapS[kqA * 4 + 3];
        uint4 u;
        u.x = tf32r(v.x); u.y = tf32r(v.y); u.z = tf32r(v.z); u.w = tf32r(v.w);
        *(uint4*)(smem + (m_l * 260 + kqA * 4) * 4) = u;
    }

    // ---- B cp.async setup
    const int rowB = tid >> 1;           // n-local within 256-wide block
    const int colF = (tid & 1) * 16;
    const uint32_t bDstOff = (uint32_t)(rowB * 144 + colF * 4);

    const int lrow = lane & 7, l8 = (lane >> 3) & 1, l16 = (lane >> 4) & 1;
    const uint32_t aLd = sb + (uint32_t)(((wm * 32 + lrow + l8 * 8) * 260 + l16 * 4) * 4);
    const uint32_t bLd0 = (uint32_t)(((wn * 64 + lrow + l16 * 8) * 36 + l8 * 4) * 4);

    float acc[2][8][4];
#pragma unroll
    for (int a = 0; a < 2; a++)
#pragma unroll
        for (int b = 0; b < 8; b++)
#pragma unroll
            for (int c = 0; c < 4; c++) acc[a][b][c] = 0.f;

    // prologue: issue B(0)
    {
        uint32_t bD = sb + 133120u + bDstOff;
        const float* bS = g_W2t + rowB * 256 + colF;
        cpa16(bD, bS); cpa16(bD + 16, bS + 4); cpa16(bD + 32, bS + 8); cpa16(bD + 48, bS + 12);
        CP_COMMIT;
    }

    for (int it = 0; it < 32; ++it) {    // it = nb*8 + kc
        const int kc = it & 7;
        if (it < 31) {
            int nn = it + 1;
            uint32_t bD = sb + 133120u + (((nn) & 1) ? 36864u : 0u) + bDstOff;
            const float* bS = g_W2t + (((nn) >> 3) * 256 + rowB) * 256 + ((nn) & 7) * 32 + colF;
            cpa16(bD, bS); cpa16(bD + 16, bS + 4); cpa16(bD + 32, bS + 8); cpa16(bD + 48, bS + 12);
            CP_COMMIT;
        }
        if (it < 31) { CP_WAIT1; } else { CP_WAIT0; }
        __syncthreads();
        const uint32_t aB = aLd + (uint32_t)(kc * 128);   // kc*32 floats
        const uint32_t bB = sb + 133120u + ((it & 1) ? 36864u : 0u) + bLd0;
#pragma unroll
        for (int k8 = 0; k8 < 4; ++k8) {
            uint32_t af[2][4], bf[4][4];
            ldsm4(af[0], aB + k8 * 32);
            ldsm4(af[1], aB + k8 * 32 + 16 * 1040);
#pragma unroll
            for (int i = 0; i < 4; ++i) ldsm4(bf[i], bB + k8 * 32 + i * 16 * 144);
#pragma unroll
            for (int ms = 0; ms < 2; ++ms)
#pragma unroll
                for (int i = 0; i < 4; ++i) {
                    mma8(acc[ms][2 * i + 0], af[ms], bf[i][0], bf[i][1]);
                    mma8(acc[ms][2 * i + 1], af[ms], bf[i][2], bf[i][3]);
                }
        }
        if (kc == 7) {
            // ---- epilogue for n-block nb: bias+relu -> iDWT -> +identity
            const int nb = it >> 3;
#pragma unroll
            for (int ms = 0; ms < 2; ++ms) {
#pragma unroll
                for (int hf = 0; hf < 2; ++hf) {
                    int m_l = wm * 32 + ms * 16 + (lane >> 2) + hf * 8;
                    int hw = hw0 + m_l;
                    int h = hw / 80, w = hw - h * 80;
#pragma unroll
                    for (int ns = 0; ns < 8; ++ns) {
                        int jc = nb * 256 + wn * 64 + ns * 8 + (lane & 3) * 2;
                        float v0 = fmaxf(acc[ms][ns][hf * 2 + 0] + biasS[jc], 0.f);
                        float v1 = fmaxf(acc[ms][ns][hf * 2 + 1] + biasS[jc + 1], 0.f);
                        // laneE(v0,v1)=(ll,lh); laneO(v0,v1)=(hl,hh)
                        float p = v0 + v1;
                        float r = v0 - v1;
                        float op = __shfl_xor_sync(0xffffffffu, p, 1);
                        float orr = __shfl_xor_sync(0xffffffffu, r, 1);
                        float e0, e1;
                        if (lane & 1) {         // bottom row: oc, od
                            e0 = 0.5f * (orr + r);
                            e1 = 0.5f * (orr - r);
                        } else {                // top row: oa, ob
                            e0 = 0.5f * (p + op);
                            e1 = 0.5f * (p - op);
                        }
                        int cp = jc >> 2;
                        long base = (((long)bb * 256 + cp) * 160 + 2 * h + (lane & 1)) * 160 + 2 * w;
                        float2 xi = *(const float2*)(x + base);
                        *(float2*)(out + base) = make_float2(e0 + xi.x, e1 + xi.y);
                    }
                }
            }
#pragma unroll
            for (int a = 0; a < 2; a++)
#pragma unroll
                for (int b = 0; b < 8; b++)
#pragma unroll
                    for (int c = 0; c < 4; c++) acc[a][b][c] = 0.f;
        }
        __syncthreads();
    }
}

// ---------------- host launch ---------------------------------------------
extern "C" void kernel_launch(void* const* d_in, const int* in_sizes, int n_in,
                              void* d_out, int out_size) {
    (void)in_sizes; (void)n_in; (void)out_size;
    const float* x        = (const float*)d_in[0];
    const float* fusion_w = (const float*)d_in[1];
    const float* fusion_b = (const float*)d_in[2];
    const float* bn1_g    = (const float*)d_in[3];
    const float* bn1_b    = (const float*)d_in[4];
    const float* bn1_m    = (const float*)d_in[5];
    const float* bn1_v    = (const float*)d_in[6];
    const float* sa_w     = (const float*)d_in[7];
    const float* ca_w1    = (const float*)d_in[8];
    const float* ca_w2    = (const float*)d_in[9];
    const float* proj_w   = (const float*)d_in[10];
    const float* proj_b   = (const float*)d_in[11];
    const float* bn2_g    = (const float*)d_in[12];
    const float* bn2_b    = (const float*)d_in[13];
    const float* bn2_m    = (const float*)d_in[14];
    const float* bn2_v    = (const float*)d_in[15];
    float* out = (float*)d_out;

    cudaFuncSetAttribute(gemm1, cudaFuncAttributeMaxDynamicSharedMemorySize, G1_SMEM);
    cudaFuncSetAttribute(gemm2, cudaFuncAttributeMaxDynamicSharedMemorySize, G2_SMEM);

    prep<<<(2 * K1 * N1) / 256, 256>>>(fusion_w, fusion_b, bn1_g, bn1_b, bn1_m, bn1_v,
                                       proj_w, proj_b, bn2_g, bn2_b, bn2_m, bn2_v);
    gemm1<<<MTOT / 128, 512, G1_SMEM>>>(x);
    spconv<<<MTOT / 256, 256>>>(sa_w);
    chstats_part<<<BQ * 8 * NSEG, 256>>>();
    chmlp<<<BQ, 256>>>(ca_w1, ca_w2);
    gemm2<<<MTOT / 128, 512, G2_SMEM>>>(x, out);
}

// round 6
// speedup vs baseline: 4.3758x; 1.5454x over previous
#include <cuda_runtime.h>
#include <cuda_fp16.h>
#include <cstdint>

// ---------------- problem constants ----------------
#define BQ    8
#define HWQ   6400          // 80*80
#define MTOT  51200         // 8*6400
#define K1    1024
#define N1    256
#define K2    256
#define N2    1024
#define NSEG  25            // 6400 / 256

// ---------------- scratch (device globals) --------
__device__ __align__(16) __half g_W1h[N1 * K1];      // [n][k] fp16 (DWT+BN1 folded)
__device__ __align__(16) float  g_bias1[N1];
__device__ __align__(16) __half g_W2h[N2 * K2];      // [j][k] fp16, j = c'*4+g (permuted)
__device__ __align__(16) float  g_bias2p[N2];
__device__ __align__(16) float  g_fused[(long)MTOT * 256];
__device__ __align__(16) float  g_avg_sp[MTOT];
__device__ __align__(16) float  g_max_sp[MTOT];
__device__ __align__(16) float  g_gate[MTOT];
__device__ __align__(16) float  g_chsum_part[NSEG * BQ * 256];
__device__ __align__(16) float  g_chmax_part[NSEG * BQ * 256];
__device__ __align__(16) float  g_chmap[BQ * 256];

// ---------------- PTX helpers ----------------------
__device__ __forceinline__ uint32_t smem_u32(const void* p) {
    uint32_t a;
    asm("{ .reg .u64 t; cvta.to.shared.u64 t, %1; cvt.u32.u64 %0, t; }" : "=r"(a) : "l"(p));
    return a;
}
__device__ __forceinline__ void ldsm4(uint32_t* r, uint32_t addr) {
    asm volatile("ldmatrix.sync.aligned.m8n8.x4.shared.b16 {%0,%1,%2,%3}, [%4];"
                 : "=r"(r[0]), "=r"(r[1]), "=r"(r[2]), "=r"(r[3]) : "r"(addr));
}
// fp16 mma, fp32 accumulate, k16
__device__ __forceinline__ void mma16(float* d, const uint32_t* a, uint32_t b0, uint32_t b1) {
    asm volatile(
        "mma.sync.aligned.m16n8k16.row.col.f32.f16.f16.f32 "
        "{%0,%1,%2,%3}, {%4,%5,%6,%7}, {%8,%9}, {%0,%1,%2,%3};"
        : "+f"(d[0]), "+f"(d[1]), "+f"(d[2]), "+f"(d[3])
        : "r"(a[0]), "r"(a[1]), "r"(a[2]), "r"(a[3]), "r"(b0), "r"(b1));
}
__device__ __forceinline__ void cpa16(uint32_t dst, const void* src) {
    asm volatile("cp.async.cg.shared.global [%0], [%1], 16;" :: "r"(dst), "l"(src));
}
#define CP_COMMIT asm volatile("cp.async.commit_group;" ::: "memory")
#define CP_WAIT1  asm volatile("cp.async.wait_group 1;" ::: "memory")
#define CP_WAIT0  asm volatile("cp.async.wait_group 0;" ::: "memory")

// ---------------- prep: fold DWT+BN1 into W1 [n][k]; BN2+permute into W2 [j][k]
__global__ void prep(const float* __restrict__ fw, const float* __restrict__ fb,
                     const float* __restrict__ g1, const float* __restrict__ b1,
                     const float* __restrict__ m1, const float* __restrict__ v1,
                     const float* __restrict__ pw, const float* __restrict__ pb,
                     const float* __restrict__ g2, const float* __restrict__ b2,
                     const float* __restrict__ m2, const float* __restrict__ v2) {
    int idx = blockIdx.x * blockDim.x + threadIdx.x;
    if (idx < K1 * N1) {
        int o = idx & 255;
        int k = idx >> 8;            // k = c*4 + q, q = 2*dy + dx
        int c = k >> 2, q = k & 3;
        float inv = g1[o] * rsqrtf(v1[o] + 1e-5f);
        float slh = (q < 2) ? 1.f : -1.f;
        float shl = ((q & 1) == 0) ? 1.f : -1.f;
        float shh = slh * shl;
        float val = fw[o * 1024 + c]
                  + slh * fw[o * 1024 + 256 + c]
                  + shl * fw[o * 1024 + 512 + c]
                  + shh * fw[o * 1024 + 768 + c];
        g_W1h[o * 1024 + k] = __float2half_rn(0.5f * inv * val);
        if (k == 0) g_bias1[o] = fb[o] * inv + b1[o] - m1[o] * inv;
    } else {
        int idx2 = idx - K1 * N1;
        int j = idx2 & 1023;          // j = c'*4 + g
        int k = idx2 >> 10;
        int o = (j & 3) * 256 + (j >> 2);
        float inv = g2[o] * rsqrtf(v2[o] + 1e-5f);
        g_W2h[j * 256 + k] = __float2half_rn(pw[o * 256 + k] * inv);
        if (k == 0) g_bias2p[j] = pb[o] * inv + b2[o] - m2[o] * inv;
    }
}

// ============================================================================
// GEMM1 (fp16 HMMA k16): CTA 128m x 256n (full N), 16 warps 4m x 4n,
// warp tile 32x64, k-chunk 64 (16 chunks).
// A: DWT gather from x -> fp16 -> STS. B: cp.async of pre-converted fp16.
// Epilogue: bias+relu -> g_fused (fp32); per-pixel channel sum/max.
// smem rows padded to 144B (72 halves). A: 128x144B x2, B: 256x144B x2.
// A0@0 A1@18432 B0@36864 B1@73728 bias@110592(1024) redS@111616 redM@113664
// total 115712
// ============================================================================
#define G1_SMEM 115712
__global__ __launch_bounds__(512) void gemm1(const float* __restrict__ x) {
    extern __shared__ char smem[];
    const uint32_t sb = smem_u32(smem);
    const int tid = threadIdx.x;
    const int lane = tid & 31, warp = tid >> 5;
    const int wm = warp & 3, wn = warp >> 2;
    const int m0 = blockIdx.x * 128;
    const int bb = m0 / HWQ;
    const int hw0 = m0 % HWQ;

    if (tid < 64) ((float4*)(smem + 110592))[tid] = ((const float4*)g_bias1)[tid];

    // ---- A gather setup (chunk ch covers channels ch*16 .. ch*16+15)
    const int cA = tid >> 7;             // 0..3 ; groups at cA, cA+4, cA+8, cA+12
    const int dyA = (tid >> 6) & 1;
    const int mlA = (tid & 63) * 2;      // even local m (even w: float4 stays in row)
    const int hwA = hw0 + mlA;
    const int hA = hwA / 80, wA = hwA - hA * 80;
    const float* aBase = x + (long)bb * 256 * 25600 + cA * 25600 + (2 * hA + dyA) * 160 + 2 * wA;
    const int aCol = cA * 8 + dyA * 4;   // byte col for group 0; +32 per group

    // ---- B cp.async setup: 256 rows x 64 halves (128B) per chunk
    const int rowB = tid >> 1;
    const int colH = (tid & 1) * 32;     // half offset in chunk row (0 or 32 -> 64B)
    const __half* bSrcBase = g_W1h + rowB * 1024 + colH;
    const uint32_t bDstOff = (uint32_t)(rowB * 144 + colH * 2);

    // ---- ldsm lane bases
    const uint32_t aLd = sb + (uint32_t)((wm * 32 + (lane & 15)) * 144 + (lane >> 4) * 16);
    const uint32_t bLd = sb + 36864u + (uint32_t)((wn * 64 + (lane & 15)) * 144 + (lane >> 4) * 16);

    float acc[2][8][4];
#pragma unroll
    for (int a = 0; a < 2; a++)
#pragma unroll
        for (int b = 0; b < 8; b++)
#pragma unroll
            for (int c = 0; c < 4; c++) acc[a][b][c] = 0.f;

    // prologue: issue B(0); prefetch A(0)
    {
        uint32_t bD = sb + 36864u + bDstOff;
        const __half* bS = bSrcBase;
        cpa16(bD, bS); cpa16(bD + 16, bS + 8); cpa16(bD + 32, bS + 16); cpa16(bD + 48, bS + 24);
        CP_COMMIT;
    }
    float4 aR[4];
#pragma unroll
    for (int i = 0; i < 4; ++i) aR[i] = *(const float4*)(aBase + i * 4 * 25600);

    for (int it = 0; it < 16; ++it) {
        const uint32_t aOff = (it & 1) ? 18432u : 0u;
        if (it < 15) {  // issue B(it+1)
            uint32_t bD = sb + 36864u + (((it + 1) & 1) ? 36864u : 0u) + bDstOff;
            const __half* bS = bSrcBase + (it + 1) * 64;
            cpa16(bD, bS); cpa16(bD + 16, bS + 8); cpa16(bD + 32, bS + 16); cpa16(bD + 48, bS + 24);
            CP_COMMIT;
        }
        // STS A(it): 4 channel groups x 2 rows, half2 each
#pragma unroll
        for (int i = 0; i < 4; ++i) {
            __half2 h01 = __floats2half2_rn(aR[i].x, aR[i].y);
            __half2 h23 = __floats2half2_rn(aR[i].z, aR[i].w);
            *(__half2*)(smem + aOff + mlA * 144 + aCol + i * 32) = h01;
            *(__half2*)(smem + aOff + (mlA + 1) * 144 + aCol + i * 32) = h23;
        }
        if (it < 15) { CP_WAIT1; } else { CP_WAIT0; }
        __syncthreads();
        if (it < 15) {  // prefetch next A (16 channels ahead)
#pragma unroll
            for (int i = 0; i < 4; ++i)
                aR[i] = *(const float4*)(aBase + (long)(it + 1) * 409600 + i * 4 * 25600);
        }
        const uint32_t aB = aLd + aOff;
        const uint32_t bB = bLd + ((it & 1) ? 36864u : 0u);
#pragma unroll
        for (int kk = 0; kk < 4; ++kk) {   // 4 x k16
            uint32_t af[2][4], bf[4][4];
            ldsm4(af[0], aB + kk * 32);
            ldsm4(af[1], aB + kk * 32 + 16 * 144);
#pragma unroll
            for (int i = 0; i < 4; ++i) ldsm4(bf[i], bB + kk * 32 + i * 16 * 144);
#pragma unroll
            for (int ms = 0; ms < 2; ++ms)
#pragma unroll
                for (int i = 0; i < 4; ++i) {
                    mma16(acc[ms][2 * i + 0], af[ms], bf[i][0], bf[i][2]);
                    mma16(acc[ms][2 * i + 1], af[ms], bf[i][1], bf[i][3]);
                }
        }
        __syncthreads();
    }

    // ---- epilogue: bias+relu -> g_fused; full-row sum/max
    const float* biasS = (const float*)(smem + 110592);
    float* redS = (float*)(smem + 111616);
    float* redM = (float*)(smem + 113664);
    float rs[2][2] = {{0.f, 0.f}, {0.f, 0.f}};
    float rm[2][2] = {{0.f, 0.f}, {0.f, 0.f}};
#pragma unroll
    for (int ms = 0; ms < 2; ++ms) {
        int row0 = m0 + wm * 32 + ms * 16 + (lane >> 2);
#pragma unroll
        for (int ns = 0; ns < 8; ++ns) {
            int col = wn * 64 + ns * 8 + (lane & 3) * 2;
            float b0 = biasS[col], b1 = biasS[col + 1];
            float v0 = fmaxf(acc[ms][ns][0] + b0, 0.f);
            float v1 = fmaxf(acc[ms][ns][1] + b1, 0.f);
            *(float2*)(g_fused + (long)row0 * 256 + col) = make_float2(v0, v1);
            rs[ms][0] += v0 + v1;
            rm[ms][0] = fmaxf(rm[ms][0], fmaxf(v0, v1));
            float v2 = fmaxf(acc[ms][ns][2] + b0, 0.f);
            float v3 = fmaxf(acc[ms][ns][3] + b1, 0.f);
            *(float2*)(g_fused + (long)(row0 + 8) * 256 + col) = make_float2(v2, v3);
            rs[ms][1] += v2 + v3;
            rm[ms][1] = fmaxf(rm[ms][1], fmaxf(v2, v3));
        }
    }
#pragma unroll
    for (int ms = 0; ms < 2; ++ms)
#pragma unroll
        for (int hf = 0; hf < 2; ++hf) {
            float s = rs[ms][hf], mx = rm[ms][hf];
            s += __shfl_xor_sync(0xffffffffu, s, 1);
            s += __shfl_xor_sync(0xffffffffu, s, 2);
            mx = fmaxf(mx, __shfl_xor_sync(0xffffffffu, mx, 1));
            mx = fmaxf(mx, __shfl_xor_sync(0xffffffffu, mx, 2));
            if ((lane & 3) == 0) {
                int r_l = wm * 32 + ms * 16 + (lane >> 2) + hf * 8;
                redS[r_l * 4 + wn] = s;
                redM[r_l * 4 + wn] = mx;
            }
        }
    __syncthreads();
    if (tid < 128) {
        float s = redS[tid * 4] + redS[tid * 4 + 1] + redS[tid * 4 + 2] + redS[tid * 4 + 3];
        float mx = fmaxf(fmaxf(redM[tid * 4], redM[tid * 4 + 1]),
                         fmaxf(redM[tid * 4 + 2], redM[tid * 4 + 3]));
        g_avg_sp[m0 + tid] = s * (1.f / 256.f);
        g_max_sp[m0 + tid] = mx;
    }
}

// ---------------- spconv: 7x7 spatial conv + sigmoid -----------------------
__global__ void spconv(const float* __restrict__ sa_w) {
    __shared__ float sw[98];
    if (threadIdx.x < 98) sw[threadIdx.x] = sa_w[threadIdx.x];
    __syncthreads();
    int m = blockIdx.x * 256 + threadIdx.x;
    int bb = m / HWQ, hw = m % HWQ;
    int h = hw / 80, w = hw % 80;
    float acc = 0.f;
#pragma unroll
    for (int ky = 0; ky < 7; ky++) {
        int y = h + ky - 3;
        if ((unsigned)y < 80u) {
#pragma unroll
            for (int kx = 0; kx < 7; kx++) {
                int xx = w + kx - 3;
                if ((unsigned)xx < 80u) {
                    int mi = bb * HWQ + y * 80 + xx;
                    acc += g_avg_sp[mi] * sw[ky * 7 + kx]
                         + g_max_sp[mi] * sw[49 + ky * 7 + kx];
                }
            }
        }
    }
    g_gate[m] = 1.f / (1.f + expf(-acc));
}

// ---------------- chstats: per-(b,c) sum/max of gate*fused, partials -------
__global__ void chstats_part() {
    int bid = blockIdx.x;                 // 8*8*25 = 1600
    int bb = bid / 200;
    int rem = bid % 200;
    int cg = rem / NSEG;
    int seg = rem % NSEG;
    int cl = threadIdx.x & 31;
    int r0 = threadIdx.x >> 5;
    int c = cg * 32 + cl;
    float s = 0.f, mx = 0.f;
    for (int r = r0; r < 256; r += 8) {
        int m = bb * HWQ + seg * 256 + r;
        float v = g_gate[m] * g_fused[(long)m * 256 + c];
        s += v;
        mx = fmaxf(mx, v);
    }
    __shared__ float ss[256], sm_[256];
    ss[threadIdx.x] = s;
    sm_[threadIdx.x] = mx;
    __syncthreads();
    if (r0 == 0) {
#pragma unroll
        for (int r = 1; r < 8; r++) {
            s += ss[r * 32 + cl];
            mx = fmaxf(mx, sm_[r * 32 + cl]);
        }
        g_chsum_part[(seg * BQ + bb) * 256 + c] = s;
        g_chmax_part[(seg * BQ + bb) * 256 + c] = mx;
    }
}

// ---------------- chmlp: finalize stats + channel MLP + sigmoid ------------
__global__ void chmlp(const float* __restrict__ w1, const float* __restrict__ w2) {
    int bb = blockIdx.x;
    int tid = threadIdx.x;
    __shared__ float sA[256], sM[256], sH[32];
    float s = 0.f, mx = 0.f;
    for (int seg = 0; seg < NSEG; seg++) {
        s += g_chsum_part[(seg * BQ + bb) * 256 + tid];
        mx = fmaxf(mx, g_chmax_part[(seg * BQ + bb) * 256 + tid]);
    }
    sA[tid] = s * (1.f / 6400.f);
    sM[tid] = mx;
    __syncthreads();
    int warp = tid >> 5, lane = tid & 31;
#pragma unroll
    for (int it = 0; it < 4; it++) {
        int t = warp * 4 + it;            // 0..31
        int u = t & 15, which = t >> 4;
        const float* vec = which ? sM : sA;
        float d = 0.f;
        for (int cc = lane; cc < 256; cc += 32) d += w1[u * 256 + cc] * vec[cc];
#pragma unroll
        for (int off = 16; off; off >>= 1) d += __shfl_xor_sync(0xffffffffu, d, off);
        if (lane == 0) sH[t] = fmaxf(d, 0.f);
    }
    __syncthreads();
    float o = 0.f;
#pragma unroll
    for (int u = 0; u < 16; u++) o += w2[tid * 16 + u] * (sH[u] + sH[16 + u]);
    g_chmap[bb * 256 + tid] = 1.f / (1.f + expf(-o));
}

// ============================================================================
// GEMM2 (fp16 HMMA k16): full-K gated A tile resident in fp16 (128 x 264h,
// 528B rows). 4 n-blocks of 256, k-chunk 64 via cp.async double buffer.
// Warp tile 32x64. Epilogue: bias+relu -> iDWT (shfl) -> +identity -> out.
// smem: A@0(67584) B0@67584(36864) B1@104448 bias@141312(4096)
//       cmap@145408(1024) gate@146432(512)  total 146944
// ============================================================================
#define G2_SMEM 146944
__global__ __launch_bounds__(512) void gemm2(const float* __restrict__ x,
                                             float* __restrict__ out) {
    extern __shared__ char smem[];
    const uint32_t sb = smem_u32(smem);
    const int tid = threadIdx.x;
    const int lane = tid & 31, warp = tid >> 5;
    const int wm = warp & 3, wn = warp >> 2;
    const int m0 = blockIdx.x * 128;
    const int bb = m0 / HWQ;
    const int hw0 = m0 % HWQ;

    float* biasS = (float*)(smem + 141312);
    float* cmapS = (float*)(smem + 145408);
    float* gateS = (float*)(smem + 146432);
    if (tid < 256) ((float4*)biasS)[tid] = ((const float4*)g_bias2p)[tid];
    if (tid < 64) ((float4*)cmapS)[tid] = ((const float4*)(g_chmap + bb * 256))[tid];
    if (tid < 32) ((float4*)gateS)[tid] = ((const float4*)(g_gate + m0))[tid];

    // ---- B cp.async setup
    const int rowB = tid >> 1;           // n-local within 256-wide block
    const int colH = (tid & 1) * 32;     // halves (0 or 32 -> 64B)
    const uint32_t bDstOff = (uint32_t)(rowB * 144 + colH * 2);

    // prologue: issue B(0) (independent of A fill)
    {
        uint32_t bD = sb + 67584u + bDstOff;
        const __half* bS = g_W2h + rowB * 256 + colH;
        cpa16(bD, bS); cpa16(bD + 16, bS + 8); cpa16(bD + 32, bS + 16); cpa16(bD + 48, bS + 24);
        CP_COMMIT;
    }
    __syncthreads();   // gate/cmap visible for A fill

    // ---- fill full-K A tile: fused * gate * cmap -> fp16 (row pad 264 halves)
    const int kqA = tid & 63;
    const int ml0 = tid >> 6;
#pragma unroll
    for (int i = 0; i < 16; ++i) {
        int m_l = ml0 + i * 8;
        float4 v = *(const float4*)(g_fused + (long)(m0 + m_l) * 256 + kqA * 4);
        float gm = gateS[m_l];
        v.x *= gm * cmapS[kqA * 4 + 0];
        v.y *= gm * cmapS[kqA * 4 + 1];
        v.z *= gm * cmapS[kqA * 4 + 2];
        v.w *= gm * cmapS[kqA * 4 + 3];
        __half2 h01 = __floats2half2_rn(v.x, v.y);
        __half2 h23 = __floats2half2_rn(v.z, v.w);
        *(__half2*)(smem + m_l * 528 + kqA * 8) = h01;
        *(__half2*)(smem + m_l * 528 + kqA * 8 + 4) = h23;
    }

    const uint32_t aLd = sb + (uint32_t)((wm * 32 + (lane & 15)) * 528 + (lane >> 4) * 16);
    const uint32_t bLd0 = (uint32_t)((wn * 64 + (lane & 15)) * 144 + (lane >> 4) * 16);

    float acc[2][8][4];
#pragma unroll
    for (int a = 0; a < 2; a++)
#pragma unroll
        for (int b = 0; b < 8; b++)
#pragma unroll
            for (int c = 0; c < 4; c++) acc[a][b][c] = 0.f;

    for (int it = 0; it < 16; ++it) {    // it = nb*4 + kc
        const int kc = it & 3;
        if (it < 15) {
            int nn = it + 1;
            uint32_t bD = sb + 67584u + ((nn & 1) ? 36864u : 0u) + bDstOff;
            const __half* bS = g_W2h + ((nn >> 2) * 256 + rowB) * 256 + (nn & 3) * 64 + colH;
            cpa16(bD, bS); cpa16(bD + 16, bS + 8); cpa16(bD + 32, bS + 16); cpa16(bD + 48, bS + 24);
            CP_COMMIT;
        }
        if (it < 15) { CP_WAIT1; } else { CP_WAIT0; }
        __syncthreads();   // also covers A-fill completion at it=0
        const uint32_t aB = aLd + (uint32_t)(kc * 128);   // kc * 64 halves
        const uint32_t bB = sb + 67584u + ((it & 1) ? 36864u : 0u) + bLd0;
#pragma unroll
        for (int kk = 0; kk < 4; ++kk) {
            uint32_t af[2][4], bf[4][4];
            ldsm4(af[0], aB + kk * 32);
            ldsm4(af[1], aB + kk * 32 + 16 * 528);
#pragma unroll
            for (int i = 0; i < 4; ++i) ldsm4(bf[i], bB + kk * 32 + i * 16 * 144);
#pragma unroll
            for (int ms = 0; ms < 2; ++ms)
#pragma unroll
                for (int i = 0; i < 4; ++i) {
                    mma16(acc[ms][2 * i + 0], af[ms], bf[i][0], bf[i][2]);
                    mma16(acc[ms][2 * i + 1], af[ms], bf[i][1], bf[i][3]);
                }
        }
        if (kc == 3) {
            // ---- epilogue for n-block nb: bias+relu -> iDWT -> +identity
            const int nb = it >> 2;
#pragma unroll
            for (int ms = 0; ms < 2; ++ms) {
#pragma unroll
                for (int hf = 0; hf < 2; ++hf) {
                    int m_l = wm * 32 + ms * 16 + (lane >> 2) + hf * 8;
                    int hw = hw0 + m_l;
                    int h = hw / 80, w = hw - h * 80;
#pragma unroll
                    for (int ns = 0; ns < 8; ++ns) {
                        int jc = nb * 256 + wn * 64 + ns * 8 + (lane & 3) * 2;
                        float v0 = fmaxf(acc[ms][ns][hf * 2 + 0] + biasS[jc], 0.f);
                        float v1 = fmaxf(acc[ms][ns][hf * 2 + 1] + biasS[jc + 1], 0.f);
                        // laneE(v0,v1)=(ll,lh); laneO(v0,v1)=(hl,hh)
                        float p = v0 + v1;
                        float r = v0 - v1;
                        float op = __shfl_xor_sync(0xffffffffu, p, 1);
                        float orr = __shfl_xor_sync(0xffffffffu, r, 1);
                        float e0, e1;
                        if (lane & 1) {         // bottom row: oc, od
                            e0 = 0.5f * (orr + r);
                            e1 = 0.5f * (orr - r);
                        } else {                // top row: oa, ob
                            e0 = 0.5f * (p + op);
                            e1 = 0.5f * (p - op);
                        }
                        int cp = jc >> 2;
                        long base = (((long)bb * 256 + cp) * 160 + 2 * h + (lane & 1)) * 160 + 2 * w;
                        float2 xi = *(const float2*)(x + base);
                        *(float2*)(out + base) = make_float2(e0 + xi.x, e1 + xi.y);
                    }
                }
            }
#pragma unroll
            for (int a = 0; a < 2; a++)
#pragma unroll
                for (int b = 0; b < 8; b++)
#pragma unroll
                    for (int c = 0; c < 4; c++) acc[a][b][c] = 0.f;
        }
        __syncthreads();
    }
}

// ---------------- host launch ---------------------------------------------
extern "C" void kernel_launch(void* const* d_in, const int* in_sizes, int n_in,
                              void* d_out, int out_size) {
    (void)in_sizes; (void)n_in; (void)out_size;
    const float* x        = (const float*)d_in[0];
    const float* fusion_w = (const float*)d_in[1];
    const float* fusion_b = (const float*)d_in[2];
    const float* bn1_g    = (const float*)d_in[3];
    const float* bn1_b    = (const float*)d_in[4];
    const float* bn1_m    = (const float*)d_in[5];
    const float* bn1_v    = (const float*)d_in[6];
    const float* sa_w     = (const float*)d_in[7];
    const float* ca_w1    = (const float*)d_in[8];
    const float* ca_w2    = (const float*)d_in[9];
    const float* proj_w   = (const float*)d_in[10];
    const float* proj_b   = (const float*)d_in[11];
    const float* bn2_g    = (const float*)d_in[12];
    const float* bn2_b    = (const float*)d_in[13];
    const float* bn2_m    = (const float*)d_in[14];
    const float* bn2_v    = (const float*)d_in[15];
    float* out = (float*)d_out;

    cudaFuncSetAttribute(gemm1, cudaFuncAttributeMaxDynamicSharedMemorySize, G1_SMEM);
    cudaFuncSetAttribute(gemm2, cudaFuncAttributeMaxDynamicSharedMemorySize, G2_SMEM);

    prep<<<(2 * K1 * N1) / 256, 256>>>(fusion_w, fusion_b, bn1_g, bn1_b, bn1_m, bn1_v,
                                       proj_w, proj_b, bn2_g, bn2_b, bn2_m, bn2_v);
    gemm1<<<MTOT / 128, 512, G1_SMEM>>>(x);
    spconv<<<MTOT / 256, 256>>>(sa_w);
    chstats_part<<<BQ * 8 * NSEG, 256>>>();
    chmlp<<<BQ, 256>>>(ca_w1, ca_w2);
    gemm2<<<MTOT / 128, 512, G2_SMEM>>>(x, out);
}

// round 7
// speedup vs baseline: 4.3890x; 1.0030x over previous
#include <cuda_runtime.h>
#include <cuda_fp16.h>
#include <cstdint>

// ---------------- problem constants ----------------
#define BQ    8
#define HWQ   6400          // 80*80
#define MTOT  51200         // 8*6400
#define K1    1024
#define N1    256
#define K2    256
#define N2    1024
#define NSEG  25            // 6400 / 256

// ---------------- scratch (device globals) --------
__device__ __align__(16) __half g_W1h[N1 * K1];      // [n][k] fp16 (DWT+BN1 folded)
__device__ __align__(16) float  g_bias1[N1];
__device__ __align__(16) __half g_W2h[N2 * K2];      // [j][k] fp16, j = c'*4+g (permuted)
__device__ __align__(16) float  g_bias2p[N2];
__device__ __align__(16) __half g_fused[(long)MTOT * 256];   // fp16 now (26 MB)
__device__ __align__(16) float  g_avg_sp[MTOT];
__device__ __align__(16) float  g_max_sp[MTOT];
__device__ __align__(16) float  g_gate[MTOT];
__device__ __align__(16) float  g_chsum_part[NSEG * BQ * 256];
__device__ __align__(16) float  g_chmax_part[NSEG * BQ * 256];
__device__ __align__(16) float  g_chmap[BQ * 256];

// ---------------- PTX helpers ----------------------
__device__ __forceinline__ uint32_t smem_u32(const void* p) {
    uint32_t a;
    asm("{ .reg .u64 t; cvta.to.shared.u64 t, %1; cvt.u32.u64 %0, t; }" : "=r"(a) : "l"(p));
    return a;
}
__device__ __forceinline__ void ldsm4(uint32_t* r, uint32_t addr) {
    asm volatile("ldmatrix.sync.aligned.m8n8.x4.shared.b16 {%0,%1,%2,%3}, [%4];"
                 : "=r"(r[0]), "=r"(r[1]), "=r"(r[2]), "=r"(r[3]) : "r"(addr));
}
__device__ __forceinline__ void mma16(float* d, const uint32_t* a, uint32_t b0, uint32_t b1) {
    asm volatile(
        "mma.sync.aligned.m16n8k16.row.col.f32.f16.f16.f32 "
        "{%0,%1,%2,%3}, {%4,%5,%6,%7}, {%8,%9}, {%0,%1,%2,%3};"
        : "+f"(d[0]), "+f"(d[1]), "+f"(d[2]), "+f"(d[3])
        : "r"(a[0]), "r"(a[1]), "r"(a[2]), "r"(a[3]), "r"(b0), "r"(b1));
}
__device__ __forceinline__ void cpa16(uint32_t dst, const void* src) {
    asm volatile("cp.async.cg.shared.global [%0], [%1], 16;" :: "r"(dst), "l"(src));
}
#define CP_COMMIT asm volatile("cp.async.commit_group;" ::: "memory")
#define CP_WAIT1  asm volatile("cp.async.wait_group 1;" ::: "memory")
#define CP_WAIT0  asm volatile("cp.async.wait_group 0;" ::: "memory")

// ---------------- prep: fold DWT+BN1 into W1 [n][k]; BN2+permute into W2 [j][k]
__global__ void prep(const float* __restrict__ fw, const float* __restrict__ fb,
                     const float* __restrict__ g1, const float* __restrict__ b1,
                     const float* __restrict__ m1, const float* __restrict__ v1,
                     const float* __restrict__ pw, const float* __restrict__ pb,
                     const float* __restrict__ g2, const float* __restrict__ b2,
                     const float* __restrict__ m2, const float* __restrict__ v2) {
    int idx = blockIdx.x * blockDim.x + threadIdx.x;
    if (idx < K1 * N1) {
        int o = idx & 255;
        int k = idx >> 8;            // k = c*4 + q, q = 2*dy + dx
        int c = k >> 2, q = k & 3;
        float inv = g1[o] * rsqrtf(v1[o] + 1e-5f);
        float slh = (q < 2) ? 1.f : -1.f;
        float shl = ((q & 1) == 0) ? 1.f : -1.f;
        float shh = slh * shl;
        float val = fw[o * 1024 + c]
                  + slh * fw[o * 1024 + 256 + c]
                  + shl * fw[o * 1024 + 512 + c]
                  + shh * fw[o * 1024 + 768 + c];
        g_W1h[o * 1024 + k] = __float2half_rn(0.5f * inv * val);
        if (k == 0) g_bias1[o] = fb[o] * inv + b1[o] - m1[o] * inv;
    } else {
        int idx2 = idx - K1 * N1;
        int j = idx2 & 1023;          // j = c'*4 + g
        int k = idx2 >> 10;
        int o = (j & 3) * 256 + (j >> 2);
        float inv = g2[o] * rsqrtf(v2[o] + 1e-5f);
        g_W2h[j * 256 + k] = __float2half_rn(pw[o * 256 + k] * inv);
        if (k == 0) g_bias2p[j] = pb[o] * inv + b2[o] - m2[o] * inv;
    }
}

// ============================================================================
// GEMM1 (fp16 HMMA k16): CTA 128m x 256n, 16 warps 4m x 4n, warp tile 32x64,
// k-chunk 64 (16 chunks). 3-stage A (STS ring) + 3-stage B (cp.async ring),
// single barrier per chunk.
// smem: A stages 3x18432 @0; B stages 3x36864 @55296; bias@165888(1024)
//       redS@166912(2048) redM@168960(2048)  total 171008
// ============================================================================
#define G1_SMEM 171008
__global__ __launch_bounds__(512) void gemm1(const float* __restrict__ x) {
    extern __shared__ char smem[];
    const uint32_t sb = smem_u32(smem);
    const int tid = threadIdx.x;
    const int lane = tid & 31, warp = tid >> 5;
    const int wm = warp & 3, wn = warp >> 2;
    const int m0 = blockIdx.x * 128;
    const int bb = m0 / HWQ;
    const int hw0 = m0 % HWQ;

    if (tid < 64) ((float4*)(smem + 165888))[tid] = ((const float4*)g_bias1)[tid];

    // ---- A gather setup (chunk ch covers channels ch*16 .. ch*16+15)
    const int cA = tid >> 7;             // 0..3 ; groups at cA, cA+4, cA+8, cA+12
    const int dyA = (tid >> 6) & 1;
    const int mlA = (tid & 63) * 2;      // even local m
    const int hwA = hw0 + mlA;
    const int hA = hwA / 80, wA = hwA - hA * 80;
    const float* aBase = x + (long)bb * 256 * 25600 + cA * 25600 + (2 * hA + dyA) * 160 + 2 * wA;
    const int aCol = cA * 8 + dyA * 4;   // byte col for group 0; +32 per group

    // ---- B cp.async setup: 256 rows x 64 halves (128B) per chunk
    const int rowB = tid >> 1;
    const int colH = (tid & 1) * 32;
    const __half* bSrcBase = g_W1h + rowB * 1024 + colH;
    const uint32_t bDstOff = (uint32_t)(rowB * 144 + colH * 2);

    // ---- ldsm lane bases
    const uint32_t aLd = sb + (uint32_t)((wm * 32 + (lane & 15)) * 144 + (lane >> 4) * 16);
    const uint32_t bLd = sb + 55296u + (uint32_t)((wn * 64 + (lane & 15)) * 144 + (lane >> 4) * 16);

    float acc[2][8][4];
#pragma unroll
    for (int a = 0; a < 2; a++)
#pragma unroll
        for (int b = 0; b < 8; b++)
#pragma unroll
            for (int c = 0; c < 4; c++) acc[a][b][c] = 0.f;

    float4 aR[4];
    // ---- prologue: A(0) -> stage0; A(1) -> regs; B(0), B(1) in flight
#pragma unroll
    for (int i = 0; i < 4; ++i) aR[i] = *(const float4*)(aBase + i * 4 * 25600);
#pragma unroll
    for (int i = 0; i < 4; ++i) {
        __half2 h01 = __floats2half2_rn(aR[i].x, aR[i].y);
        __half2 h23 = __floats2half2_rn(aR[i].z, aR[i].w);
        *(__half2*)(smem + mlA * 144 + aCol + i * 32) = h01;
        *(__half2*)(smem + (mlA + 1) * 144 + aCol + i * 32) = h23;
    }
#pragma unroll
    for (int i = 0; i < 4; ++i) aR[i] = *(const float4*)(aBase + 409600 + i * 4 * 25600);
    {
        uint32_t bD = sb + 55296u + bDstOff;
        const __half* bS = bSrcBase;
        cpa16(bD, bS); cpa16(bD + 16, bS + 8); cpa16(bD + 32, bS + 16); cpa16(bD + 48, bS + 24);
        CP_COMMIT;
        bD = sb + 55296u + 36864u + bDstOff;
        bS = bSrcBase + 64;
        cpa16(bD, bS); cpa16(bD + 16, bS + 8); cpa16(bD + 32, bS + 16); cpa16(bD + 48, bS + 24);
        CP_COMMIT;
    }

    for (int it = 0; it < 16; ++it) {
        if (it < 15) { CP_WAIT1; } else { CP_WAIT0; }
        __syncthreads();                       // A(it), B(it) visible; compute(it-1) retired
        if (it < 15) {                         // STS A(it+1) -> stage (it+1)%3
            const uint32_t aOffN = (uint32_t)(((it + 1) % 3) * 18432);
#pragma unroll
            for (int i = 0; i < 4; ++i) {
                __half2 h01 = __floats2half2_rn(aR[i].x, aR[i].y);
                __half2 h23 = __floats2half2_rn(aR[i].z, aR[i].w);
                *(__half2*)(smem + aOffN + mlA * 144 + aCol + i * 32) = h01;
                *(__half2*)(smem + aOffN + (mlA + 1) * 144 + aCol + i * 32) = h23;
            }
        }
        if (it < 14) {                         // B(it+2) -> stage (it+2)%3 ; A(it+2) -> regs
            uint32_t bD = sb + 55296u + (uint32_t)(((it + 2) % 3) * 36864) + bDstOff;
            const __half* bS = bSrcBase + (it + 2) * 64;
            cpa16(bD, bS); cpa16(bD + 16, bS + 8); cpa16(bD + 32, bS + 16); cpa16(bD + 48, bS + 24);
            CP_COMMIT;
#pragma unroll
            for (int i = 0; i < 4; ++i)
                aR[i] = *(const float4*)(aBase + (long)(it + 2) * 409600 + i * 4 * 25600);
        }
        const uint32_t aB = aLd + (uint32_t)((it % 3) * 18432);
        const uint32_t bB = bLd + (uint32_t)((it % 3) * 36864);
#pragma unroll
        for (int kk = 0; kk < 4; ++kk) {       // 4 x k16
            uint32_t af[2][4], bf[4][4];
            ldsm4(af[0], aB + kk * 32);
            ldsm4(af[1], aB + kk * 32 + 16 * 144);
#pragma unroll
            for (int i = 0; i < 4; ++i) ldsm4(bf[i], bB + kk * 32 + i * 16 * 144);
#pragma unroll
            for (int ms = 0; ms < 2; ++ms)
#pragma unroll
                for (int i = 0; i < 4; ++i) {
                    mma16(acc[ms][2 * i + 0], af[ms], bf[i][0], bf[i][2]);
                    mma16(acc[ms][2 * i + 1], af[ms], bf[i][1], bf[i][3]);
                }
        }
    }

    // ---- epilogue: bias+relu -> g_fused (fp16); full-row sum/max (fp32)
    const float* biasS = (const float*)(smem + 165888);
    float* redS = (float*)(smem + 166912);
    float* redM = (float*)(smem + 168960);
    __half2* fh2 = (__half2*)g_fused;
    float rs[2][2] = {{0.f, 0.f}, {0.f, 0.f}};
    float rm[2][2] = {{0.f, 0.f}, {0.f, 0.f}};
#pragma unroll
    for (int ms = 0; ms < 2; ++ms) {
        int row0 = m0 + wm * 32 + ms * 16 + (lane >> 2);
#pragma unroll
        for (int ns = 0; ns < 8; ++ns) {
            int col = wn * 64 + ns * 8 + (lane & 3) * 2;
            float b0 = biasS[col], b1 = biasS[col + 1];
            float v0 = fmaxf(acc[ms][ns][0] + b0, 0.f);
            float v1 = fmaxf(acc[ms][ns][1] + b1, 0.f);
            fh2[(long)row0 * 128 + (col >> 1)] = __floats2half2_rn(v0, v1);
            rs[ms][0] += v0 + v1;
            rm[ms][0] = fmaxf(rm[ms][0], fmaxf(v0, v1));
            float v2 = fmaxf(acc[ms][ns][2] + b0, 0.f);
            float v3 = fmaxf(acc[ms][ns][3] + b1, 0.f);
            fh2[(long)(row0 + 8) * 128 + (col >> 1)] = __floats2half2_rn(v2, v3);
            rs[ms][1] += v2 + v3;
            rm[ms][1] = fmaxf(rm[ms][1], fmaxf(v2, v3));
        }
    }
#pragma unroll
    for (int ms = 0; ms < 2; ++ms)
#pragma unroll
        for (int hf = 0; hf < 2; ++hf) {
            float s = rs[ms][hf], mx = rm[ms][hf];
            s += __shfl_xor_sync(0xffffffffu, s, 1);
            s += __shfl_xor_sync(0xffffffffu, s, 2);
            mx = fmaxf(mx, __shfl_xor_sync(0xffffffffu, mx, 1));
            mx = fmaxf(mx, __shfl_xor_sync(0xffffffffu, mx, 2));
            if ((lane & 3) == 0) {
                int r_l = wm * 32 + ms * 16 + (lane >> 2) + hf * 8;
                redS[r_l * 4 + wn] = s;
                redM[r_l * 4 + wn] = mx;
            }
        }
    __syncthreads();
    if (tid < 128) {
        float s = redS[tid * 4] + redS[tid * 4 + 1] + redS[tid * 4 + 2] + redS[tid * 4 + 3];
        float mx = fmaxf(fmaxf(redM[tid * 4], redM[tid * 4 + 1]),
                         fmaxf(redM[tid * 4 + 2], redM[tid * 4 + 3]));
        g_avg_sp[m0 + tid] = s * (1.f / 256.f);
        g_max_sp[m0 + tid] = mx;
    }
}

// ============================================================================
// spstats: fused 7x7 spatial conv + sigmoid gate + per-(b,c) sum/max partials.
// grid = 200 (one block per 256-pixel segment), block = 256.
// ============================================================================
__global__ void spstats(const float* __restrict__ sa_w) {
    __shared__ float sw[98];
    __shared__ float gate_s[256];
    __shared__ float ss[512], mm_[512];
    const int tid = threadIdx.x;
    if (tid < 98) sw[tid] = sa_w[tid];
    __syncthreads();
    const int m0 = blockIdx.x * 256;
    const int m = m0 + tid;
    const int bb = m0 / HWQ;
    {
        int hw = m % HWQ;
        int h = hw / 80, w = hw % 80;
        float acc = 0.f;
#pragma unroll
        for (int ky = 0; ky < 7; ky++) {
            int y = h + ky - 3;
            if ((unsigned)y < 80u) {
#pragma unroll
                for (int kx = 0; kx < 7; kx++) {
                    int xx = w + kx - 3;
                    if ((unsigned)xx < 80u) {
                        int mi = bb * HWQ + y * 80 + xx;
                        acc += g_avg_sp[mi] * sw[ky * 7 + kx]
                             + g_max_sp[mi] * sw[49 + ky * 7 + kx];
                    }
                }
            }
        }
        float g = 1.f / (1.f + expf(-acc));
        g_gate[m] = g;
        gate_s[tid] = g;
    }
    __syncthreads();
    // channel partials: thread (rp, c2) handles channels 2*c2, 2*c2+1, rows rp::2
    const int c2 = tid & 127;
    const int rp = tid >> 7;
    const __half2* fh = (const __half2*)g_fused;
    float s0 = 0.f, s1 = 0.f, x0 = 0.f, x1 = 0.f;
#pragma unroll 4
    for (int r = rp; r < 256; r += 2) {
        float gg = gate_s[r];
        float2 f = __half22float2(fh[(long)(m0 + r) * 128 + c2]);
        float a = gg * f.x, b = gg * f.y;
        s0 += a; s1 += b;
        x0 = fmaxf(x0, a); x1 = fmaxf(x1, b);
    }
    ss[(2 * c2 + 0) * 2 + rp] = s0;
    ss[(2 * c2 + 1) * 2 + rp] = s1;
    mm_[(2 * c2 + 0) * 2 + rp] = x0;
    mm_[(2 * c2 + 1) * 2 + rp] = x1;
    __syncthreads();
    const int seg = (m0 % HWQ) >> 8;
    float s = ss[tid * 2] + ss[tid * 2 + 1];
    float mx = fmaxf(mm_[tid * 2], mm_[tid * 2 + 1]);
    g_chsum_part[(seg * BQ + bb) * 256 + tid] = s;
    g_chmax_part[(seg * BQ + bb) * 256 + tid] = mx;
}

// ---------------- chmlp: finalize stats + channel MLP + sigmoid ------------
__global__ void chmlp(const float* __restrict__ w1, const float* __restrict__ w2) {
    int bb = blockIdx.x;
    int tid = threadIdx.x;
    __shared__ float sA[256], sM[256], sH[32];
    float s = 0.f, mx = 0.f;
    for (int seg = 0; seg < NSEG; seg++) {
        s += g_chsum_part[(seg * BQ + bb) * 256 + tid];
        mx = fmaxf(mx, g_chmax_part[(seg * BQ + bb) * 256 + tid]);
    }
    sA[tid] = s * (1.f / 6400.f);
    sM[tid] = mx;
    __syncthreads();
    int warp = tid >> 5, lane = tid & 31;
#pragma unroll
    for (int it = 0; it < 4; it++) {
        int t = warp * 4 + it;            // 0..31
        int u = t & 15, which = t >> 4;
        const float* vec = which ? sM : sA;
        float d = 0.f;
        for (int cc = lane; cc < 256; cc += 32) d += w1[u * 256 + cc] * vec[cc];
#pragma unroll
        for (int off = 16; off; off >>= 1) d += __shfl_xor_sync(0xffffffffu, d, off);
        if (lane == 0) sH[t] = fmaxf(d, 0.f);
    }
    __syncthreads();
    float o = 0.f;
#pragma unroll
    for (int u = 0; u < 16; u++) o += w2[tid * 16 + u] * (sH[u] + sH[16 + u]);
    g_chmap[bb * 256 + tid] = 1.f / (1.f + expf(-o));
}

// ============================================================================
// GEMM2 (fp16 HMMA k16): full-K gated A tile resident (128 x 264h, 528B rows,
// filled from fp16 g_fused). 4 n-blocks of 256, k-chunk 64, 3-stage B ring,
// single barrier per chunk. Epilogue: bias+relu -> iDWT (shfl) -> +identity.
// smem: A@0(67584) B stages 3x36864 @67584 bias@178176(4096)
//       cmap@182272(1024) gate@183296(512)  total 183808
// ============================================================================
#define G2_SMEM 183808
__global__ __launch_bounds__(512) void gemm2(const float* __restrict__ x,
                                             float* __restrict__ out) {
    extern __shared__ char smem[];
    const uint32_t sb = smem_u32(smem);
    const int tid = threadIdx.x;
    const int lane = tid & 31, warp = tid >> 5;
    const int wm = warp & 3, wn = warp >> 2;
    const int m0 = blockIdx.x * 128;
    const int bb = m0 / HWQ;
    const int hw0 = m0 % HWQ;

    float* biasS = (float*)(smem + 178176);
    float* cmapS = (float*)(smem + 182272);
    float* gateS = (float*)(smem + 183296);
    if (tid < 256) ((float4*)biasS)[tid] = ((const float4*)g_bias2p)[tid];
    if (tid < 64) ((float4*)cmapS)[tid] = ((const float4*)(g_chmap + bb * 256))[tid];
    if (tid < 32) ((float4*)gateS)[tid] = ((const float4*)(g_gate + m0))[tid];

    // ---- B cp.async setup
    const int rowB = tid >> 1;
    const int colH = (tid & 1) * 32;
    const uint32_t bDstOff = (uint32_t)(rowB * 144 + colH * 2);

    // prologue: B(0), B(1) in flight (independent of A fill)
    {
        uint32_t bD = sb + 67584u + bDstOff;
        const __half* bS = g_W2h + rowB * 256 + colH;
        cpa16(bD, bS); cpa16(bD + 16, bS + 8); cpa16(bD + 32, bS + 16); cpa16(bD + 48, bS + 24);
        CP_COMMIT;
        bD = sb + 67584u + 36864u + bDstOff;
        bS = g_W2h + rowB * 256 + 64 + colH;   // nn=1 -> nb=0, kc=1
        cpa16(bD, bS); cpa16(bD + 16, bS + 8); cpa16(bD + 32, bS + 16); cpa16(bD + 48, bS + 24);
        CP_COMMIT;
    }
    __syncthreads();   // gate/cmap visible for A fill

    // ---- fill full-K A tile: fused(fp16) * gate * cmap -> fp16 (row pad 264h)
    const int kqA = tid & 63;            // handles channels kqA*4 .. +3
    const int ml0 = tid >> 6;
    const __half2* fh = (const __half2*)g_fused;
#pragma unroll
    for (int i = 0; i < 16; ++i) {
        int m_l = ml0 + i * 8;
        float2 f01 = __half22float2(fh[(long)(m0 + m_l) * 128 + kqA * 2]);
        float2 f23 = __half22float2(fh[(long)(m0 + m_l) * 128 + kqA * 2 + 1]);
        float gm = gateS[m_l];
        f01.x *= gm * cmapS[kqA * 4 + 0];
        f01.y *= gm * cmapS[kqA * 4 + 1];
        f23.x *= gm * cmapS[kqA * 4 + 2];
        f23.y *= gm * cmapS[kqA * 4 + 3];
        *(__half2*)(smem + m_l * 528 + kqA * 8) = __floats2half2_rn(f01.x, f01.y);
        *(__half2*)(smem + m_l * 528 + kqA * 8 + 4) = __floats2half2_rn(f23.x, f23.y);
    }

    const uint32_t aLd = sb + (uint32_t)((wm * 32 + (lane & 15)) * 528 + (lane >> 4) * 16);
    const uint32_t bLd0 = (uint32_t)((wn * 64 + (lane & 15)) * 144 + (lane >> 4) * 16);

    float acc[2][8][4];
#pragma unroll
    for (int a = 0; a < 2; a++)
#pragma unroll
        for (int b = 0; b < 8; b++)
#pragma unroll
            for (int c = 0; c < 4; c++) acc[a][b][c] = 0.f;

    for (int it = 0; it < 16; ++it) {    // it = nb*4 + kc
        const int kc = it & 3;
        if (it < 15) { CP_WAIT1; } else { CP_WAIT0; }
        __syncthreads();                 // B(it) + (at it=0) A fill visible
        if (it < 14) {                   // B(it+2) -> stage (it+2)%3
            int nn = it + 2;
            uint32_t bD = sb + 67584u + (uint32_t)((nn % 3) * 36864) + bDstOff;
            const __half* bS = g_W2h + ((nn >> 2) * 256 + rowB) * 256 + (nn & 3) * 64 + colH;
            cpa16(bD, bS); cpa16(bD + 16, bS + 8); cpa16(bD + 32, bS + 16); cpa16(bD + 48, bS + 24);
            CP_COMMIT;
        }
        const uint32_t aB = aLd + (uint32_t)(kc * 128);   // kc * 64 halves
        const uint32_t bB = sb + 67584u + (uint32_t)((it % 3) * 36864) + bLd0;
#pragma unroll
        for (int kk = 0; kk < 4; ++kk) {
            uint32_t af[2][4], bf[4][4];
            ldsm4(af[0], aB + kk * 32);
            ldsm4(af[1], aB + kk * 32 + 16 * 528);
#pragma unroll
            for (int i = 0; i < 4; ++i) ldsm4(bf[i], bB + kk * 32 + i * 16 * 144);
#pragma unroll
            for (int ms = 0; ms < 2; ++ms)
#pragma unroll
                for (int i = 0; i < 4; ++i) {
                    mma16(acc[ms][2 * i + 0], af[ms], bf[i][0], bf[i][2]);
                    mma16(acc[ms][2 * i + 1], af[ms], bf[i][1], bf[i][3]);
                }
        }
        if (kc == 3) {
            // ---- epilogue for n-block nb: bias+relu -> iDWT -> +identity
            const int nb = it >> 2;
#pragma unroll
            for (int ms = 0; ms < 2; ++ms) {
#pragma unroll
                for (int hf = 0; hf < 2; ++hf) {
                    int m_l = wm * 32 + ms * 16 + (lane >> 2) + hf * 8;
                    int hw = hw0 + m_l;
                    int h = hw / 80, w = hw - h * 80;
#pragma unroll
                    for (int ns = 0; ns < 8; ++ns) {
                        int jc = nb * 256 + wn * 64 + ns * 8 + (lane & 3) * 2;
                        float v0 = fmaxf(acc[ms][ns][hf * 2 + 0] + biasS[jc], 0.f);
                        float v1 = fmaxf(acc[ms][ns][hf * 2 + 1] + biasS[jc + 1], 0.f);
                        float p = v0 + v1;
                        float r = v0 - v1;
                        float op = __shfl_xor_sync(0xffffffffu, p, 1);
                        float orr = __shfl_xor_sync(0xffffffffu, r, 1);
                        float e0, e1;
                        if (lane & 1) {         // bottom row: oc, od
                            e0 = 0.5f * (orr + r);
                            e1 = 0.5f * (orr - r);
                        } else {                // top row: oa, ob
                            e0 = 0.5f * (p + op);
                            e1 = 0.5f * (p - op);
                        }
                        int cp = jc >> 2;
                        long base = (((long)bb * 256 + cp) * 160 + 2 * h + (lane & 1)) * 160 + 2 * w;
                        float2 xi = *(const float2*)(x + base);
                        *(float2*)(out + base) = make_float2(e0 + xi.x, e1 + xi.y);
                    }
                }
            }
#pragma unroll
            for (int a = 0; a < 2; a++)
#pragma unroll
                for (int b = 0; b < 8; b++)
#pragma unroll
                    for (int c = 0; c < 4; c++) acc[a][b][c] = 0.f;
        }
    }
}

// ---------------- host launch ---------------------------------------------
extern "C" void kernel_launch(void* const* d_in, const int* in_sizes, int n_in,
                              void* d_out, int out_size) {
    (void)in_sizes; (void)n_in; (void)out_size;
    const float* x        = (const float*)d_in[0];
    const float* fusion_w = (const float*)d_in[1];
    const float* fusion_b = (const float*)d_in[2];
    const float* bn1_g    = (const float*)d_in[3];
    const float* bn1_b    = (const float*)d_in[4];
    const float* bn1_m    = (const float*)d_in[5];
    const float* bn1_v    = (const float*)d_in[6];
    const float* sa_w     = (const float*)d_in[7];
    const float* ca_w1    = (const float*)d_in[8];
    const float* ca_w2    = (const float*)d_in[9];
    const float* proj_w   = (const float*)d_in[10];
    const float* proj_b   = (const float*)d_in[11];
    const float* bn2_g    = (const float*)d_in[12];
    const float* bn2_b    = (const float*)d_in[13];
    const float* bn2_m    = (const float*)d_in[14];
    const float* bn2_v    = (const float*)d_in[15];
    float* out = (float*)d_out;

    cudaFuncSetAttribute(gemm1, cudaFuncAttributeMaxDynamicSharedMemorySize, G1_SMEM);
    cudaFuncSetAttribute(gemm2, cudaFuncAttributeMaxDynamicSharedMemorySize, G2_SMEM);

    prep<<<(2 * K1 * N1) / 256, 256>>>(fusion_w, fusion_b, bn1_g, bn1_b, bn1_m, bn1_v,
                                       proj_w, proj_b, bn2_g, bn2_b, bn2_m, bn2_v);
    gemm1<<<MTOT / 128, 512, G1_SMEM>>>(x);
    spstats<<<MTOT / 256, 256>>>(sa_w);
    chmlp<<<BQ, 256>>>(ca_w1, ca_w2);
    gemm2<<<MTOT / 128, 512, G2_SMEM>>>(x, out);
}